// round 1
// baseline (speedup 1.0000x reference)
#include <cuda_runtime.h>
#include <cuda_bf16.h>
#include <cstdint>

#define NA 100000
#define NB 100000
#define D 64

// ---------------- scratch (device globals; no allocation allowed) ----------
__device__ int   g_deg_aa[NA];
__device__ int   g_deg_ba[NA];
__device__ int   g_deg_ab[NB];
__device__ float g_hA1[NA * D];
__device__ float g_hB1[NB * D];
__device__ float g_HWaa[NA * D];
__device__ float g_HWab[NA * D];
__device__ float g_HWba[NB * D];
__device__ float g_raa[NA * D];
__device__ float g_rba[NA * D];
__device__ float g_rab[NB * D];
__device__ float g_vec[5 * D];   // cA, u_aa, u_ba, cB, u_ab

// ---------------- zero scratch ----------------------------------------------
__global__ void k_zero() {
    int i = blockIdx.x * blockDim.x + threadIdx.x;
    int stride = gridDim.x * blockDim.x;
    const int nf4 = NA * D / 4;
    float4 z = make_float4(0.f, 0.f, 0.f, 0.f);
    for (int j = i; j < nf4; j += stride) {
        reinterpret_cast<float4*>(g_raa)[j] = z;
        reinterpret_cast<float4*>(g_rba)[j] = z;
        reinterpret_cast<float4*>(g_rab)[j] = z;
    }
    for (int j = i; j < NA; j += stride) {
        g_deg_aa[j] = 0; g_deg_ba[j] = 0; g_deg_ab[j] = 0;
    }
}

// ---------------- in-degree histogram ---------------------------------------
__global__ void k_deg(const int* __restrict__ dst, int* __restrict__ deg, int E) {
    int i = blockIdx.x * blockDim.x + threadIdx.x;
    if (i < E) atomicAdd(&deg[dst[i]], 1);
}

// ---------------- layer-0 closed-form vectors --------------------------------
__global__ void k_small(const float* __restrict__ embA, const float* __restrict__ embB,
                        const float* __restrict__ Waa, const float* __restrict__ baa,
                        const float* __restrict__ Wab, const float* __restrict__ bab,
                        const float* __restrict__ Wba, const float* __restrict__ bba,
                        const float* __restrict__ WnA, const float* __restrict__ bnA,
                        const float* __restrict__ WnB, const float* __restrict__ bnB) {
    __shared__ float sA[D], sB[D], vaa[D], vab[D], vba[D];
    int c = threadIdx.x;
    sA[c] = embA[c]; sB[c] = embB[c];
    __syncthreads();
    float a0 = baa[c], a1 = bab[c], a2 = bba[c];
    for (int k = 0; k < D; k++) {
        a0 += sA[k] * Waa[k * D + c];
        a1 += sA[k] * Wab[k * D + c];
        a2 += sB[k] * Wba[k * D + c];
    }
    vaa[c] = fmaxf(a0, 0.f); vab[c] = fmaxf(a1, 0.f); vba[c] = fmaxf(a2, 0.f);
    __syncthreads();
    float cA = bnA[c], uaa = 0.f, uba = 0.f, cB = bnB[c], uab = 0.f;
    for (int k = 0; k < D; k++) {
        cA  += sA[k]  * WnA[k * D + c];
        uaa += vaa[k] * WnA[(D + k) * D + c];
        uba += vba[k] * WnA[(2 * D + k) * D + c];
        cB  += sB[k]  * WnB[k * D + c];
        uab += vab[k] * WnB[(D + k) * D + c];
    }
    g_vec[c] = cA; g_vec[D + c] = uaa; g_vec[2 * D + c] = uba;
    g_vec[3 * D + c] = cB; g_vec[4 * D + c] = uab;
}

// ---------------- layer-0 node states from degrees ---------------------------
__global__ void k_h1() {
    int t = blockIdx.x * blockDim.x + threadIdx.x;
    if (t >= (NA + NB) * 16) return;
    int node = t >> 4;
    int c = (t & 15) * 4;
    float4 o;
    if (node < NA) {
        float d1 = (float)g_deg_aa[node], d2 = (float)g_deg_ba[node];
        o.x = fmaxf(g_vec[c + 0] + d1 * g_vec[D + c + 0] + d2 * g_vec[2 * D + c + 0], 0.f);
        o.y = fmaxf(g_vec[c + 1] + d1 * g_vec[D + c + 1] + d2 * g_vec[2 * D + c + 1], 0.f);
        o.z = fmaxf(g_vec[c + 2] + d1 * g_vec[D + c + 2] + d2 * g_vec[2 * D + c + 2], 0.f);
        o.w = fmaxf(g_vec[c + 3] + d1 * g_vec[D + c + 3] + d2 * g_vec[2 * D + c + 3], 0.f);
        reinterpret_cast<float4*>(g_hA1)[node * 16 + (c >> 2)] = o;
    } else {
        int nb = node - NA;
        float d = (float)g_deg_ab[nb];
        o.x = fmaxf(g_vec[3 * D + c + 0] + d * g_vec[4 * D + c + 0], 0.f);
        o.y = fmaxf(g_vec[3 * D + c + 1] + d * g_vec[4 * D + c + 1], 0.f);
        o.z = fmaxf(g_vec[3 * D + c + 2] + d * g_vec[4 * D + c + 2], 0.f);
        o.w = fmaxf(g_vec[3 * D + c + 3] + d * g_vec[4 * D + c + 3], 0.f);
        reinterpret_cast<float4*>(g_hB1)[nb * 16 + (c >> 2)] = o;
    }
}

// ---------------- per-node message tables: O = relu(H @ W + b) ---------------
__global__ void __launch_bounds__(256) k_gemm_relu(
        const float* __restrict__ H, const float* __restrict__ W,
        const float* __restrict__ b, float* __restrict__ O, int N) {
    __shared__ float sW[D * D];
    for (int i = threadIdx.x; i < D * D; i += blockDim.x) sW[i] = W[i];
    __syncthreads();
    int row = blockIdx.x * (blockDim.x / 32) + (threadIdx.x >> 5);
    if (row >= N) return;
    int lane = threadIdx.x & 31;
    const float* h = H + (size_t)row * D;
    float h0 = h[lane], h1 = h[lane + 32];
    float acc0 = b[lane], acc1 = b[lane + 32];
#pragma unroll
    for (int k = 0; k < 32; k++) {
        float hv = __shfl_sync(0xffffffffu, h0, k);
        acc0 += hv * sW[k * D + lane];
        acc1 += hv * sW[k * D + lane + 32];
    }
#pragma unroll
    for (int k = 0; k < 32; k++) {
        float hv = __shfl_sync(0xffffffffu, h1, k);
        acc0 += hv * sW[(32 + k) * D + lane];
        acc1 += hv * sW[(32 + k) * D + lane + 32];
    }
    O[(size_t)row * D + lane]      = fmaxf(acc0, 0.f);
    O[(size_t)row * D + lane + 32] = fmaxf(acc1, 0.f);
}

// ---------------- edge scatter: r[dst] += HWtab[src] --------------------------
__global__ void k_scatter(const int* __restrict__ src, const int* __restrict__ dst,
                          const float* __restrict__ tab, float* __restrict__ r, int E) {
    int t = blockIdx.x * blockDim.x + threadIdx.x;
    int e = t >> 4;
    if (e >= E) return;
    int q = t & 15;
    int s = src[e], d = dst[e];
    float4 v = reinterpret_cast<const float4*>(tab + (size_t)s * D)[q];
    float* p = r + (size_t)d * D + q * 4;
    asm volatile("red.global.add.v4.f32 [%0], {%1,%2,%3,%4};"
                 :: "l"(p), "f"(v.x), "f"(v.y), "f"(v.z), "f"(v.w) : "memory");
}

// ---------------- node update A: out = relu([h, r_aa, r_ba] @ WnA + bn) -------
__global__ void __launch_bounds__(256) k_nodeA(const float* __restrict__ Wn,
                                               const float* __restrict__ bn,
                                               float* __restrict__ out) {
    __shared__ float sW[3 * D * D];  // 48 KB
    for (int i = threadIdx.x; i < 3 * D * D; i += blockDim.x) sW[i] = Wn[i];
    __syncthreads();
    int row = blockIdx.x * (blockDim.x / 32) + (threadIdx.x >> 5);
    if (row >= NA) return;
    int lane = threadIdx.x & 31;
    float acc0 = bn[lane], acc1 = bn[lane + 32];
    const float* base[3] = { g_hA1 + (size_t)row * D,
                             g_raa + (size_t)row * D,
                             g_rba + (size_t)row * D };
#pragma unroll
    for (int s = 0; s < 3; s++) {
        float x0 = base[s][lane], x1 = base[s][lane + 32];
#pragma unroll
        for (int k = 0; k < 32; k++) {
            float hv = __shfl_sync(0xffffffffu, x0, k);
            acc0 += hv * sW[(s * 64 + k) * D + lane];
            acc1 += hv * sW[(s * 64 + k) * D + lane + 32];
        }
#pragma unroll
        for (int k = 0; k < 32; k++) {
            float hv = __shfl_sync(0xffffffffu, x1, k);
            acc0 += hv * sW[(s * 64 + 32 + k) * D + lane];
            acc1 += hv * sW[(s * 64 + 32 + k) * D + lane + 32];
        }
    }
    out[(size_t)row * D + lane]      = fmaxf(acc0, 0.f);
    out[(size_t)row * D + lane + 32] = fmaxf(acc1, 0.f);
}

// ---------------- node update B: out = relu([h, r_ab] @ WnB + bn) -------------
__global__ void __launch_bounds__(256) k_nodeB(const float* __restrict__ Wn,
                                               const float* __restrict__ bn,
                                               float* __restrict__ out) {
    __shared__ float sW[2 * D * D];  // 32 KB
    for (int i = threadIdx.x; i < 2 * D * D; i += blockDim.x) sW[i] = Wn[i];
    __syncthreads();
    int row = blockIdx.x * (blockDim.x / 32) + (threadIdx.x >> 5);
    if (row >= NB) return;
    int lane = threadIdx.x & 31;
    float acc0 = bn[lane], acc1 = bn[lane + 32];
    const float* base[2] = { g_hB1 + (size_t)row * D,
                             g_rab + (size_t)row * D };
#pragma unroll
    for (int s = 0; s < 2; s++) {
        float x0 = base[s][lane], x1 = base[s][lane + 32];
#pragma unroll
        for (int k = 0; k < 32; k++) {
            float hv = __shfl_sync(0xffffffffu, x0, k);
            acc0 += hv * sW[(s * 64 + k) * D + lane];
            acc1 += hv * sW[(s * 64 + k) * D + lane + 32];
        }
#pragma unroll
        for (int k = 0; k < 32; k++) {
            float hv = __shfl_sync(0xffffffffu, x1, k);
            acc0 += hv * sW[(s * 64 + 32 + k) * D + lane];
            acc1 += hv * sW[(s * 64 + 32 + k) * D + lane + 32];
        }
    }
    out[(size_t)row * D + lane]      = fmaxf(acc0, 0.f);
    out[(size_t)row * D + lane + 32] = fmaxf(acc1, 0.f);
}

// -----------------------------------------------------------------------------
extern "C" void kernel_launch(void* const* d_in, const int* in_sizes, int n_in,
                              void* d_out, int out_size) {
    const int*   src_aa = (const int*)d_in[0];
    const int*   dst_aa = (const int*)d_in[1];
    const int*   src_ab = (const int*)d_in[2];
    const int*   dst_ab = (const int*)d_in[3];
    const int*   src_ba = (const int*)d_in[4];
    const int*   dst_ba = (const int*)d_in[5];
    const float* embA   = (const float*)d_in[6];
    const float* embB   = (const float*)d_in[7];
    const float* Waa    = (const float*)d_in[8];
    const float* baa    = (const float*)d_in[9];
    const float* Wab    = (const float*)d_in[10];
    const float* bab    = (const float*)d_in[11];
    const float* Wba    = (const float*)d_in[12];
    const float* bba    = (const float*)d_in[13];
    const float* WnA    = (const float*)d_in[14];
    const float* bnA    = (const float*)d_in[15];
    const float* WnB    = (const float*)d_in[16];
    const float* bnB    = (const float*)d_in[17];
    const int Eaa = in_sizes[0];
    const int Eab = in_sizes[2];
    const int Eba = in_sizes[4];
    float* out = (float*)d_out;

    void *p_deg_aa, *p_deg_ba, *p_deg_ab;
    void *p_hA1, *p_hB1, *p_HWaa, *p_HWab, *p_HWba, *p_raa, *p_rba, *p_rab;
    cudaGetSymbolAddress(&p_deg_aa, g_deg_aa);
    cudaGetSymbolAddress(&p_deg_ba, g_deg_ba);
    cudaGetSymbolAddress(&p_deg_ab, g_deg_ab);
    cudaGetSymbolAddress(&p_hA1, g_hA1);
    cudaGetSymbolAddress(&p_hB1, g_hB1);
    cudaGetSymbolAddress(&p_HWaa, g_HWaa);
    cudaGetSymbolAddress(&p_HWab, g_HWab);
    cudaGetSymbolAddress(&p_HWba, g_HWba);
    cudaGetSymbolAddress(&p_raa, g_raa);
    cudaGetSymbolAddress(&p_rba, g_rba);
    cudaGetSymbolAddress(&p_rab, g_rab);

    // 1. zero scratch (r accumulators + degree histograms)
    k_zero<<<1024, 256>>>();

    // 2. in-degree histograms (layer-0 closed form)
    k_deg<<<(Eaa + 255) / 256, 256>>>(dst_aa, (int*)p_deg_aa, Eaa);
    k_deg<<<(Eab + 255) / 256, 256>>>(dst_ab, (int*)p_deg_ab, Eab);
    k_deg<<<(Eba + 255) / 256, 256>>>(dst_ba, (int*)p_deg_ba, Eba);

    // 3. layer-0 constant vectors
    k_small<<<1, 64>>>(embA, embB, Waa, baa, Wab, bab, Wba, bba, WnA, bnA, WnB, bnB);

    // 4. layer-0 node states from degrees
    k_h1<<<((NA + NB) * 16 + 255) / 256, 256>>>();

    // 5. layer-1 per-node message tables (hoisted edge GEMMs)
    k_gemm_relu<<<(NA + 7) / 8, 256>>>((const float*)p_hA1, Waa + 4096, baa + 64, (float*)p_HWaa, NA);
    k_gemm_relu<<<(NA + 7) / 8, 256>>>((const float*)p_hA1, Wab + 4096, bab + 64, (float*)p_HWab, NA);
    k_gemm_relu<<<(NB + 7) / 8, 256>>>((const float*)p_hB1, Wba + 4096, bba + 64, (float*)p_HWba, NB);

    // 6. edge gather + vector-RED scatter
    k_scatter<<<(int)(((long long)Eaa * 16 + 255) / 256), 256>>>(src_aa, dst_aa, (const float*)p_HWaa, (float*)p_raa, Eaa);
    k_scatter<<<(int)(((long long)Eab * 16 + 255) / 256), 256>>>(src_ab, dst_ab, (const float*)p_HWab, (float*)p_rab, Eab);
    k_scatter<<<(int)(((long long)Eba * 16 + 255) / 256), 256>>>(src_ba, dst_ba, (const float*)p_HWba, (float*)p_rba, Eba);

    // 7. layer-1 node updates -> output (rows [0:NA]=A, [NA:]=B)
    k_nodeA<<<(NA + 7) / 8, 256>>>(WnA + 192 * 64, bnA + 64, out);
    k_nodeB<<<(NB + 7) / 8, 256>>>(WnB + 128 * 64, bnB + 64, out + (size_t)NA * D);
}

// round 2
// speedup vs baseline: 1.1229x; 1.1229x over previous
#include <cuda_runtime.h>
#include <cuda_bf16.h>
#include <cstdint>

#define NA 100000
#define NB 100000
#define D 64
#define NTOT (NA + NA + NB)                 // deg/off layout: [aa->A | ba->A | ab->B]
#define NCHUNK ((NTOT + 1023) / 1024)       // 293
#define ECAP 2000000

// ---------------- scratch (device globals; no allocation allowed) ----------
__device__ int   g_deg[NTOT];
__device__ int   g_off[NTOT + 1];
__device__ int   g_cur[NTOT];
__device__ int   g_csr[ECAP];
__device__ int   g_bsum[NCHUNK];
__device__ int   g_bsumx[NCHUNK];
__device__ float g_HWaa[NA * D];
__device__ float g_HWab[NA * D];
__device__ float g_HWba[NB * D];
__device__ float g_vec[5 * D];   // cA, u_aa, u_ba, cB, u_ab

// ---------------- zero degree histograms -------------------------------------
__global__ void k_zero_deg() {
    int i = blockIdx.x * blockDim.x + threadIdx.x;
    if (i < NTOT) g_deg[i] = 0;
}

// ---------------- in-degree histogram ----------------------------------------
__global__ void k_deg(const int* __restrict__ dst, int E, int base) {
    int i = blockIdx.x * blockDim.x + threadIdx.x;
    if (i < E) atomicAdd(&g_deg[base + dst[i]], 1);
}

// ---------------- exclusive scan (3 phases) -----------------------------------
__global__ void k_scan1() {
    __shared__ int ss[256];
    int t = threadIdx.x;
    int base = blockIdx.x * 1024 + t * 4;
    int v0 = (base + 0 < NTOT) ? g_deg[base + 0] : 0;
    int v1 = (base + 1 < NTOT) ? g_deg[base + 1] : 0;
    int v2 = (base + 2 < NTOT) ? g_deg[base + 2] : 0;
    int v3 = (base + 3 < NTOT) ? g_deg[base + 3] : 0;
    int s = v0 + v1 + v2 + v3;
    ss[t] = s;
    __syncthreads();
    for (int off = 1; off < 256; off <<= 1) {
        int x = (t >= off) ? ss[t - off] : 0;
        __syncthreads();
        ss[t] += x;
        __syncthreads();
    }
    int excl = ss[t] - s;
    if (t == 255) g_bsum[blockIdx.x] = ss[255];
    int run = excl;
    if (base + 0 < NTOT) { g_off[base + 0] = run; run += v0; }
    if (base + 1 < NTOT) { g_off[base + 1] = run; run += v1; }
    if (base + 2 < NTOT) { g_off[base + 2] = run; run += v2; }
    if (base + 3 < NTOT) { g_off[base + 3] = run; }
}

__global__ void k_scan2() {
    __shared__ int ss[512];
    int t = threadIdx.x;
    int orig = (t < NCHUNK) ? g_bsum[t] : 0;
    ss[t] = orig;
    __syncthreads();
    for (int off = 1; off < 512; off <<= 1) {
        int x = (t >= off) ? ss[t - off] : 0;
        __syncthreads();
        ss[t] += x;
        __syncthreads();
    }
    if (t < NCHUNK) g_bsumx[t] = ss[t] - orig;
    if (t == 511) g_off[NTOT] = ss[511];
}

__global__ void k_scan3() {
    int i = blockIdx.x * blockDim.x + threadIdx.x;
    if (i < NTOT) {
        int v = g_off[i] + g_bsumx[i >> 10];
        g_off[i] = v;
        g_cur[i] = v;
    }
}

// ---------------- counting-sort fill: group src by dst ------------------------
__global__ void k_fill(const int* __restrict__ src, const int* __restrict__ dst,
                       int E, int base) {
    int i = blockIdx.x * blockDim.x + threadIdx.x;
    if (i < E) {
        int pos = atomicAdd(&g_cur[base + dst[i]], 1);
        g_csr[pos] = src[i];
    }
}

// ---------------- layer-0 closed-form vectors --------------------------------
__global__ void k_small(const float* __restrict__ embA, const float* __restrict__ embB,
                        const float* __restrict__ Waa, const float* __restrict__ baa,
                        const float* __restrict__ Wab, const float* __restrict__ bab,
                        const float* __restrict__ Wba, const float* __restrict__ bba,
                        const float* __restrict__ WnA, const float* __restrict__ bnA,
                        const float* __restrict__ WnB, const float* __restrict__ bnB) {
    __shared__ float sA[D], sB[D], vaa[D], vab[D], vba[D];
    int c = threadIdx.x;
    sA[c] = embA[c]; sB[c] = embB[c];
    __syncthreads();
    float a0 = baa[c], a1 = bab[c], a2 = bba[c];
    for (int k = 0; k < D; k++) {
        a0 += sA[k] * Waa[k * D + c];
        a1 += sA[k] * Wab[k * D + c];
        a2 += sB[k] * Wba[k * D + c];
    }
    vaa[c] = fmaxf(a0, 0.f); vab[c] = fmaxf(a1, 0.f); vba[c] = fmaxf(a2, 0.f);
    __syncthreads();
    float cA = bnA[c], uaa = 0.f, uba = 0.f, cB = bnB[c], uab = 0.f;
    for (int k = 0; k < D; k++) {
        cA  += sA[k]  * WnA[k * D + c];
        uaa += vaa[k] * WnA[(D + k) * D + c];
        uba += vba[k] * WnA[(2 * D + k) * D + c];
        cB  += sB[k]  * WnB[k * D + c];
        uab += vab[k] * WnB[(D + k) * D + c];
    }
    g_vec[c] = cA; g_vec[D + c] = uaa; g_vec[2 * D + c] = uba;
    g_vec[3 * D + c] = cB; g_vec[4 * D + c] = uab;
}

// ---------------- message tables for A-src edge types (aa, ab) ----------------
// h row recomputed from degrees + g_vec; two 64x64 GEMMs fused in one pass.
__global__ void __launch_bounds__(256) k_msgA(const float* __restrict__ Waa,
                                              const float* __restrict__ baa,
                                              const float* __restrict__ Wab,
                                              const float* __restrict__ bab) {
    __shared__ float sWaa[D * D], sWab[D * D], sv[3 * D], sb[2 * D];
    for (int i = threadIdx.x; i < D * D; i += blockDim.x) {
        sWaa[i] = Waa[i];
        sWab[i] = Wab[i];
    }
    for (int i = threadIdx.x; i < 3 * D; i += blockDim.x) sv[i] = g_vec[i];
    for (int i = threadIdx.x; i < D; i += blockDim.x) {
        sb[i] = baa[i]; sb[D + i] = bab[i];
    }
    __syncthreads();
    int row = blockIdx.x * (blockDim.x / 32) + (threadIdx.x >> 5);
    if (row >= NA) return;
    int lane = threadIdx.x & 31;
    float d1 = (float)(g_off[row + 1] - g_off[row]);            // deg_aa
    float d2 = (float)(g_off[NA + row + 1] - g_off[NA + row]);  // deg_ba
    float h0 = fmaxf(sv[lane]      + d1 * sv[D + lane]      + d2 * sv[2 * D + lane], 0.f);
    float h1 = fmaxf(sv[lane + 32] + d1 * sv[D + lane + 32] + d2 * sv[2 * D + lane + 32], 0.f);
    float a0 = sb[lane], a1 = sb[lane + 32];
    float c0 = sb[D + lane], c1 = sb[D + lane + 32];
#pragma unroll
    for (int k = 0; k < 32; k++) {
        float hv = __shfl_sync(0xffffffffu, h0, k);
        a0 += hv * sWaa[k * D + lane];      a1 += hv * sWaa[k * D + lane + 32];
        c0 += hv * sWab[k * D + lane];      c1 += hv * sWab[k * D + lane + 32];
    }
#pragma unroll
    for (int k = 0; k < 32; k++) {
        float hv = __shfl_sync(0xffffffffu, h1, k);
        a0 += hv * sWaa[(32 + k) * D + lane];      a1 += hv * sWaa[(32 + k) * D + lane + 32];
        c0 += hv * sWab[(32 + k) * D + lane];      c1 += hv * sWab[(32 + k) * D + lane + 32];
    }
    g_HWaa[(size_t)row * D + lane]      = fmaxf(a0, 0.f);
    g_HWaa[(size_t)row * D + lane + 32] = fmaxf(a1, 0.f);
    g_HWab[(size_t)row * D + lane]      = fmaxf(c0, 0.f);
    g_HWab[(size_t)row * D + lane + 32] = fmaxf(c1, 0.f);
}

// ---------------- message table for B-src edges (ba) --------------------------
__global__ void __launch_bounds__(256) k_msgB(const float* __restrict__ Wba,
                                              const float* __restrict__ bba) {
    __shared__ float sW[D * D], sv[2 * D], sb[D];
    for (int i = threadIdx.x; i < D * D; i += blockDim.x) sW[i] = Wba[i];
    for (int i = threadIdx.x; i < 2 * D; i += blockDim.x) sv[i] = g_vec[3 * D + i];
    for (int i = threadIdx.x; i < D; i += blockDim.x) sb[i] = bba[i];
    __syncthreads();
    int row = blockIdx.x * (blockDim.x / 32) + (threadIdx.x >> 5);
    if (row >= NB) return;
    int lane = threadIdx.x & 31;
    float d = (float)(g_off[2 * NA + row + 1] - g_off[2 * NA + row]);  // deg_ab
    float h0 = fmaxf(sv[lane]      + d * sv[D + lane], 0.f);
    float h1 = fmaxf(sv[lane + 32] + d * sv[D + lane + 32], 0.f);
    float a0 = sb[lane], a1 = sb[lane + 32];
#pragma unroll
    for (int k = 0; k < 32; k++) {
        float hv = __shfl_sync(0xffffffffu, h0, k);
        a0 += hv * sW[k * D + lane];  a1 += hv * sW[k * D + lane + 32];
    }
#pragma unroll
    for (int k = 0; k < 32; k++) {
        float hv = __shfl_sync(0xffffffffu, h1, k);
        a0 += hv * sW[(32 + k) * D + lane];  a1 += hv * sW[(32 + k) * D + lane + 32];
    }
    g_HWba[(size_t)row * D + lane]      = fmaxf(a0, 0.f);
    g_HWba[(size_t)row * D + lane + 32] = fmaxf(a1, 0.f);
}

// ---------------- fused reduce + node update A --------------------------------
// out = relu([h, sum HWaa[src], sum HWba[src]] @ WnA1 + bnA1)
__global__ void __launch_bounds__(256) k_nodeA(const float* __restrict__ Wn,
                                               const float* __restrict__ bn,
                                               float* __restrict__ out) {
    __shared__ float sW[3 * D * D];  // 48 KB
    __shared__ float sv[3 * D];
    for (int i = threadIdx.x; i < 3 * D * D; i += blockDim.x) sW[i] = Wn[i];
    for (int i = threadIdx.x; i < 3 * D; i += blockDim.x) sv[i] = g_vec[i];
    __syncthreads();
    int row = blockIdx.x * (blockDim.x / 32) + (threadIdx.x >> 5);
    if (row >= NA) return;
    int lane = threadIdx.x & 31;

    int beg0 = g_off[row],      end0 = g_off[row + 1];
    int beg1 = g_off[NA + row], end1 = g_off[NA + row + 1];
    float d1 = (float)(end0 - beg0), d2 = (float)(end1 - beg1);
    float h0 = fmaxf(sv[lane]      + d1 * sv[D + lane]      + d2 * sv[2 * D + lane], 0.f);
    float h1 = fmaxf(sv[lane + 32] + d1 * sv[D + lane + 32] + d2 * sv[2 * D + lane + 32], 0.f);

    float ra0 = 0.f, ra1 = 0.f, rb0 = 0.f, rb1 = 0.f;
    for (int j = beg0; j < end0; j++) {
        int s = g_csr[j];
        ra0 += g_HWaa[(size_t)s * D + lane];
        ra1 += g_HWaa[(size_t)s * D + lane + 32];
    }
    for (int j = beg1; j < end1; j++) {
        int s = g_csr[j];
        rb0 += g_HWba[(size_t)s * D + lane];
        rb1 += g_HWba[(size_t)s * D + lane + 32];
    }

    float acc0 = bn[lane], acc1 = bn[lane + 32];
#pragma unroll
    for (int k = 0; k < 32; k++) {
        float hv = __shfl_sync(0xffffffffu, h0, k);
        acc0 += hv * sW[k * D + lane]; acc1 += hv * sW[k * D + lane + 32];
    }
#pragma unroll
    for (int k = 0; k < 32; k++) {
        float hv = __shfl_sync(0xffffffffu, h1, k);
        acc0 += hv * sW[(32 + k) * D + lane]; acc1 += hv * sW[(32 + k) * D + lane + 32];
    }
#pragma unroll
    for (int k = 0; k < 32; k++) {
        float hv = __shfl_sync(0xffffffffu, ra0, k);
        acc0 += hv * sW[(64 + k) * D + lane]; acc1 += hv * sW[(64 + k) * D + lane + 32];
    }
#pragma unroll
    for (int k = 0; k < 32; k++) {
        float hv = __shfl_sync(0xffffffffu, ra1, k);
        acc0 += hv * sW[(96 + k) * D + lane]; acc1 += hv * sW[(96 + k) * D + lane + 32];
    }
#pragma unroll
    for (int k = 0; k < 32; k++) {
        float hv = __shfl_sync(0xffffffffu, rb0, k);
        acc0 += hv * sW[(128 + k) * D + lane]; acc1 += hv * sW[(128 + k) * D + lane + 32];
    }
#pragma unroll
    for (int k = 0; k < 32; k++) {
        float hv = __shfl_sync(0xffffffffu, rb1, k);
        acc0 += hv * sW[(160 + k) * D + lane]; acc1 += hv * sW[(160 + k) * D + lane + 32];
    }
    out[(size_t)row * D + lane]      = fmaxf(acc0, 0.f);
    out[(size_t)row * D + lane + 32] = fmaxf(acc1, 0.f);
}

// ---------------- fused reduce + node update B --------------------------------
__global__ void __launch_bounds__(256) k_nodeB(const float* __restrict__ Wn,
                                               const float* __restrict__ bn,
                                               float* __restrict__ out) {
    __shared__ float sW[2 * D * D];  // 32 KB
    __shared__ float sv[2 * D];
    for (int i = threadIdx.x; i < 2 * D * D; i += blockDim.x) sW[i] = Wn[i];
    for (int i = threadIdx.x; i < 2 * D; i += blockDim.x) sv[i] = g_vec[3 * D + i];
    __syncthreads();
    int row = blockIdx.x * (blockDim.x / 32) + (threadIdx.x >> 5);
    if (row >= NB) return;
    int lane = threadIdx.x & 31;

    int beg = g_off[2 * NA + row], end = g_off[2 * NA + row + 1];
    float d = (float)(end - beg);
    float h0 = fmaxf(sv[lane]      + d * sv[D + lane], 0.f);
    float h1 = fmaxf(sv[lane + 32] + d * sv[D + lane + 32], 0.f);

    float r0 = 0.f, r1 = 0.f;
    for (int j = beg; j < end; j++) {
        int s = g_csr[j];
        r0 += g_HWab[(size_t)s * D + lane];
        r1 += g_HWab[(size_t)s * D + lane + 32];
    }

    float acc0 = bn[lane], acc1 = bn[lane + 32];
#pragma unroll
    for (int k = 0; k < 32; k++) {
        float hv = __shfl_sync(0xffffffffu, h0, k);
        acc0 += hv * sW[k * D + lane]; acc1 += hv * sW[k * D + lane + 32];
    }
#pragma unroll
    for (int k = 0; k < 32; k++) {
        float hv = __shfl_sync(0xffffffffu, h1, k);
        acc0 += hv * sW[(32 + k) * D + lane]; acc1 += hv * sW[(32 + k) * D + lane + 32];
    }
#pragma unroll
    for (int k = 0; k < 32; k++) {
        float hv = __shfl_sync(0xffffffffu, r0, k);
        acc0 += hv * sW[(64 + k) * D + lane]; acc1 += hv * sW[(64 + k) * D + lane + 32];
    }
#pragma unroll
    for (int k = 0; k < 32; k++) {
        float hv = __shfl_sync(0xffffffffu, r1, k);
        acc0 += hv * sW[(96 + k) * D + lane]; acc1 += hv * sW[(96 + k) * D + lane + 32];
    }
    out[(size_t)row * D + lane]      = fmaxf(acc0, 0.f);
    out[(size_t)row * D + lane + 32] = fmaxf(acc1, 0.f);
}

// -----------------------------------------------------------------------------
extern "C" void kernel_launch(void* const* d_in, const int* in_sizes, int n_in,
                              void* d_out, int out_size) {
    const int*   src_aa = (const int*)d_in[0];
    const int*   dst_aa = (const int*)d_in[1];
    const int*   src_ab = (const int*)d_in[2];
    const int*   dst_ab = (const int*)d_in[3];
    const int*   src_ba = (const int*)d_in[4];
    const int*   dst_ba = (const int*)d_in[5];
    const float* embA   = (const float*)d_in[6];
    const float* embB   = (const float*)d_in[7];
    const float* Waa    = (const float*)d_in[8];
    const float* baa    = (const float*)d_in[9];
    const float* Wab    = (const float*)d_in[10];
    const float* bab    = (const float*)d_in[11];
    const float* Wba    = (const float*)d_in[12];
    const float* bba    = (const float*)d_in[13];
    const float* WnA    = (const float*)d_in[14];
    const float* bnA    = (const float*)d_in[15];
    const float* WnB    = (const float*)d_in[16];
    const float* bnB    = (const float*)d_in[17];
    const int Eaa = in_sizes[0];
    const int Eab = in_sizes[2];
    const int Eba = in_sizes[4];
    float* out = (float*)d_out;

    // 1. zero degree histograms
    k_zero_deg<<<(NTOT + 255) / 256, 256>>>();

    // 2. in-degree histograms (dst-grouped; layout [aa | ba | ab])
    k_deg<<<(Eaa + 255) / 256, 256>>>(dst_aa, Eaa, 0);
    k_deg<<<(Eba + 255) / 256, 256>>>(dst_ba, Eba, NA);
    k_deg<<<(Eab + 255) / 256, 256>>>(dst_ab, Eab, 2 * NA);

    // 3. exclusive scan -> CSR offsets (+ cursor copy)
    k_scan1<<<NCHUNK, 256>>>();
    k_scan2<<<1, 512>>>();
    k_scan3<<<(NTOT + 255) / 256, 256>>>();

    // 4. counting-sort fill: src ids grouped by dst
    k_fill<<<(Eaa + 255) / 256, 256>>>(src_aa, dst_aa, Eaa, 0);
    k_fill<<<(Eba + 255) / 256, 256>>>(src_ba, dst_ba, Eba, NA);
    k_fill<<<(Eab + 255) / 256, 256>>>(src_ab, dst_ab, Eab, 2 * NA);

    // 5. layer-0 closed-form vectors
    k_small<<<1, 64>>>(embA, embB, Waa, baa, Wab, bab, Wba, bba, WnA, bnA, WnB, bnB);

    // 6. layer-1 per-node message tables (h recomputed from degrees)
    k_msgA<<<(NA + 7) / 8, 256>>>(Waa + 4096, baa + 64, Wab + 4096, bab + 64);
    k_msgB<<<(NB + 7) / 8, 256>>>(Wba + 4096, bba + 64);

    // 7. fused CSR gather-reduce + node update -> output
    k_nodeA<<<(NA + 7) / 8, 256>>>(WnA + 192 * 64, bnA + 64, out);
    k_nodeB<<<(NB + 7) / 8, 256>>>(WnB + 128 * 64, bnB + 64, out + (size_t)NA * D);
}

// round 4
// speedup vs baseline: 2.0924x; 1.8634x over previous
#include <cuda_runtime.h>
#include <cuda_bf16.h>
#include <cstdint>

#define NA 100000
#define NB 100000
#define D 64
#define NTOT (NA + NA + NB)                 // deg/off layout: [aa->A | ba->A | ab->B]
#define NCHUNK ((NTOT + 1023) / 1024)
#define ECAP 2000000
#define AS 72                               // smem row stride (bf16 elems), conflict-free

// ======================= scratch =============================================
__device__ int   g_deg[NTOT];
__device__ int   g_off[NTOT + 1];
__device__ int   g_cur[NTOT];
__device__ int   g_csr[ECAP];
__device__ int   g_bsum[NCHUNK];
__device__ int   g_bsumx[NCHUNK];
__device__ float g_vec[5 * D];        // cA, u_aa, u_ba, cB, u_ab
__device__ float g_hA[NA * D];
__device__ float g_hB[NB * D];
__device__ float g_maa[NA * D];
__device__ float g_mab[NA * D];
__device__ float g_mba[NB * D];
__device__ float g_zA[NA * D];
__device__ float g_zB[NB * D];
__device__ float g_Taa[NA * D];
__device__ float g_Tab[NA * D];
__device__ float g_Tba[NB * D];

// ======================= sparse machinery ====================================
__global__ void k_zero_deg() {
    int i = blockIdx.x * blockDim.x + threadIdx.x;
    if (i < NTOT) g_deg[i] = 0;
}
__global__ void k_deg(const int* __restrict__ dst, int E, int base) {
    int i = blockIdx.x * blockDim.x + threadIdx.x;
    if (i < E) atomicAdd(&g_deg[base + dst[i]], 1);
}
__global__ void k_scan1() {
    __shared__ int ss[256];
    int t = threadIdx.x;
    int base = blockIdx.x * 1024 + t * 4;
    int v0 = (base + 0 < NTOT) ? g_deg[base + 0] : 0;
    int v1 = (base + 1 < NTOT) ? g_deg[base + 1] : 0;
    int v2 = (base + 2 < NTOT) ? g_deg[base + 2] : 0;
    int v3 = (base + 3 < NTOT) ? g_deg[base + 3] : 0;
    int s = v0 + v1 + v2 + v3;
    ss[t] = s;
    __syncthreads();
    for (int off = 1; off < 256; off <<= 1) {
        int x = (t >= off) ? ss[t - off] : 0;
        __syncthreads();
        ss[t] += x;
        __syncthreads();
    }
    int run = ss[t] - s;
    if (t == 255) g_bsum[blockIdx.x] = ss[255];
    if (base + 0 < NTOT) { g_off[base + 0] = run; run += v0; }
    if (base + 1 < NTOT) { g_off[base + 1] = run; run += v1; }
    if (base + 2 < NTOT) { g_off[base + 2] = run; run += v2; }
    if (base + 3 < NTOT) { g_off[base + 3] = run; }
}
__global__ void k_scan2() {
    __shared__ int ss[512];
    int t = threadIdx.x;
    int orig = (t < NCHUNK) ? g_bsum[t] : 0;
    ss[t] = orig;
    __syncthreads();
    for (int off = 1; off < 512; off <<= 1) {
        int x = (t >= off) ? ss[t - off] : 0;
        __syncthreads();
        ss[t] += x;
        __syncthreads();
    }
    if (t < NCHUNK) g_bsumx[t] = ss[t] - orig;
    if (t == 511) g_off[NTOT] = ss[511];
}
__global__ void k_scan3() {
    int i = blockIdx.x * blockDim.x + threadIdx.x;
    if (i < NTOT) {
        int v = g_off[i] + g_bsumx[i >> 10];
        g_off[i] = v;
        g_cur[i] = v;
    }
}
__global__ void k_fill(const int* __restrict__ src, const int* __restrict__ dst,
                       int E, int base) {
    int i = blockIdx.x * blockDim.x + threadIdx.x;
    if (i < E) {
        int pos = atomicAdd(&g_cur[base + dst[i]], 1);
        g_csr[pos] = src[i];
    }
}

// ======================= layer-0 closed form =================================
__global__ void k_small(const float* __restrict__ embA, const float* __restrict__ embB,
                        const float* __restrict__ Waa, const float* __restrict__ baa,
                        const float* __restrict__ Wab, const float* __restrict__ bab,
                        const float* __restrict__ Wba, const float* __restrict__ bba,
                        const float* __restrict__ WnA, const float* __restrict__ bnA,
                        const float* __restrict__ WnB, const float* __restrict__ bnB) {
    __shared__ float sA[D], sB[D], vaa[D], vab[D], vba[D];
    int c = threadIdx.x;
    sA[c] = embA[c]; sB[c] = embB[c];
    __syncthreads();
    float a0 = baa[c], a1 = bab[c], a2 = bba[c];
    for (int k = 0; k < D; k++) {
        a0 += sA[k] * Waa[k * D + c];
        a1 += sA[k] * Wab[k * D + c];
        a2 += sB[k] * Wba[k * D + c];
    }
    vaa[c] = fmaxf(a0, 0.f); vab[c] = fmaxf(a1, 0.f); vba[c] = fmaxf(a2, 0.f);
    __syncthreads();
    float cA = bnA[c], uaa = 0.f, uba = 0.f, cB = bnB[c], uab = 0.f;
    for (int k = 0; k < D; k++) {
        cA  += sA[k]  * WnA[k * D + c];
        uaa += vaa[k] * WnA[(D + k) * D + c];
        uba += vba[k] * WnA[(2 * D + k) * D + c];
        cB  += sB[k]  * WnB[k * D + c];
        uab += vab[k] * WnB[(D + k) * D + c];
    }
    g_vec[c] = cA; g_vec[D + c] = uaa; g_vec[2 * D + c] = uba;
    g_vec[3 * D + c] = cB; g_vec[4 * D + c] = uab;
}

// layer-0 node states (elementwise from degrees)
__global__ void k_h() {
    int idx = blockIdx.x * blockDim.x + threadIdx.x;
    if (idx >= (NA + NB) * 16) return;
    int node = idx >> 4;
    int q = (idx & 15) * 4;
    float4 o;
    if (node < NA) {
        float d1 = (float)(g_off[node + 1] - g_off[node]);
        float d2 = (float)(g_off[NA + node + 1] - g_off[NA + node]);
        o.x = fmaxf(g_vec[q + 0] + d1 * g_vec[D + q + 0] + d2 * g_vec[2 * D + q + 0], 0.f);
        o.y = fmaxf(g_vec[q + 1] + d1 * g_vec[D + q + 1] + d2 * g_vec[2 * D + q + 1], 0.f);
        o.z = fmaxf(g_vec[q + 2] + d1 * g_vec[D + q + 2] + d2 * g_vec[2 * D + q + 2], 0.f);
        o.w = fmaxf(g_vec[q + 3] + d1 * g_vec[D + q + 3] + d2 * g_vec[2 * D + q + 3], 0.f);
        reinterpret_cast<float4*>(g_hA)[node * 16 + (q >> 2)] = o;
    } else {
        int nb = node - NA;
        float d = (float)(g_off[2 * NA + nb + 1] - g_off[2 * NA + nb]);
        o.x = fmaxf(g_vec[3 * D + q + 0] + d * g_vec[4 * D + q + 0], 0.f);
        o.y = fmaxf(g_vec[3 * D + q + 1] + d * g_vec[4 * D + q + 1], 0.f);
        o.z = fmaxf(g_vec[3 * D + q + 2] + d * g_vec[4 * D + q + 2], 0.f);
        o.w = fmaxf(g_vec[3 * D + q + 3] + d * g_vec[4 * D + q + 3], 0.f);
        reinterpret_cast<float4*>(g_hB)[nb * 16 + (q >> 2)] = o;
    }
}

// ======================= HMMA GEMM (mma.sync bf16, baseline ISA) ==============
// OUT_c = maybe_relu( X[R,64] @ W_c[64,64] + b_c ),  c = 0..nc-1  (nc <= 3)
// bf16 hi/lo 3-term split for fp32-class accuracy.
__device__ __forceinline__ void mma_bf16(float c[4], const uint32_t a[4],
                                         uint32_t b0, uint32_t b1) {
    asm volatile("mma.sync.aligned.m16n8k16.row.col.f32.bf16.bf16.f32 "
                 "{%0,%1,%2,%3}, {%4,%5,%6,%7}, {%8,%9}, {%0,%1,%2,%3};"
                 : "+f"(c[0]), "+f"(c[1]), "+f"(c[2]), "+f"(c[3])
                 : "r"(a[0]), "r"(a[1]), "r"(a[2]), "r"(a[3]), "r"(b0), "r"(b1));
}

// dynamic smem layout (bf16 elems):
//   A_hi [128][AS]   offset 0
//   A_lo [128][AS]   offset 128*AS
//   per channel c: WT_hi [64][AS] at 2*128*AS + c*2*64*AS, WT_lo right after
#define SM_ALO   (128 * AS)
#define SM_W     (2 * 128 * AS)
#define SM_WCH   (2 * 64 * AS)
#define SMEM_GEMM_BYTES ((SM_W + 3 * SM_WCH) * 2)   // 92160 B

__global__ void __launch_bounds__(256) k_gemm(
        const float* __restrict__ X, int R,
        const float* __restrict__ w0, const float* __restrict__ w1, const float* __restrict__ w2,
        const float* __restrict__ b0, const float* __restrict__ b1, const float* __restrict__ b2,
        float* __restrict__ o0, float* __restrict__ o1, float* __restrict__ o2,
        int nc, int relu_mask) {
    extern __shared__ __nv_bfloat16 sm[];
    const float* wp[3] = { w0, w1, w2 };
    const float* bp[3] = { b0, b1, b2 };
    float*       op[3] = { o0, o1, o2 };
    int tid = threadIdx.x;
    int R0 = blockIdx.x * 128;

    // --- stage A (fp32 -> bf16 hi/lo) ---
    for (int i = tid; i < 128 * 64; i += 256) {
        int row = i >> 6, k = i & 63;
        float x = (R0 + row < R) ? X[(size_t)(R0 + row) * 64 + k] : 0.f;
        __nv_bfloat16 hi = __float2bfloat16(x);
        __nv_bfloat16 lo = __float2bfloat16(x - __bfloat162float(hi));
        sm[row * AS + k] = hi;
        sm[SM_ALO + row * AS + k] = lo;
    }
    // --- stage W transposed to [n][k], hi/lo ---
    for (int c = 0; c < nc; c++) {
        const float* w = wp[c];
        __nv_bfloat16* whi = sm + SM_W + c * SM_WCH;
        __nv_bfloat16* wlo = whi + 64 * AS;
        for (int i = tid; i < 64 * 64; i += 256) {
            int k = i >> 6, n = i & 63;
            float x = w[i];
            __nv_bfloat16 hi = __float2bfloat16(x);
            __nv_bfloat16 lo = __float2bfloat16(x - __bfloat162float(hi));
            whi[n * AS + k] = hi;
            wlo[n * AS + k] = lo;
        }
    }
    __syncthreads();

    int lane = tid & 31, w8 = tid >> 5;
    int g = lane >> 2, t = lane & 3;
    int rl0 = w8 * 16 + g;          // local rows rl0, rl0+8

    // --- A fragments cached in registers (shared across channels) ---
    uint32_t Ahi[16], Alo[16];
#pragma unroll
    for (int kc = 0; kc < 4; kc++) {
        int col = kc * 16 + 2 * t;
        Ahi[kc * 4 + 0] = *reinterpret_cast<const uint32_t*>(&sm[rl0 * AS + col]);
        Ahi[kc * 4 + 1] = *reinterpret_cast<const uint32_t*>(&sm[(rl0 + 8) * AS + col]);
        Ahi[kc * 4 + 2] = *reinterpret_cast<const uint32_t*>(&sm[rl0 * AS + col + 8]);
        Ahi[kc * 4 + 3] = *reinterpret_cast<const uint32_t*>(&sm[(rl0 + 8) * AS + col + 8]);
        Alo[kc * 4 + 0] = *reinterpret_cast<const uint32_t*>(&sm[SM_ALO + rl0 * AS + col]);
        Alo[kc * 4 + 1] = *reinterpret_cast<const uint32_t*>(&sm[SM_ALO + (rl0 + 8) * AS + col]);
        Alo[kc * 4 + 2] = *reinterpret_cast<const uint32_t*>(&sm[SM_ALO + rl0 * AS + col + 8]);
        Alo[kc * 4 + 3] = *reinterpret_cast<const uint32_t*>(&sm[SM_ALO + (rl0 + 8) * AS + col + 8]);
    }

    int row0 = R0 + rl0, row1 = row0 + 8;
    for (int c = 0; c < nc; c++) {
        const __nv_bfloat16* whi = sm + SM_W + c * SM_WCH;
        const __nv_bfloat16* wlo = whi + 64 * AS;
        float acc[8][4];
#pragma unroll
        for (int nt = 0; nt < 8; nt++) {
            acc[nt][0] = 0.f; acc[nt][1] = 0.f; acc[nt][2] = 0.f; acc[nt][3] = 0.f;
        }
        // term 0: Ahi * Whi, term 1: Ahi * Wlo, term 2: Alo * Whi
#pragma unroll
        for (int term = 0; term < 3; term++) {
            const uint32_t* af = (term == 2) ? Alo : Ahi;
            const __nv_bfloat16* bt = (term == 1) ? wlo : whi;
#pragma unroll
            for (int nt = 0; nt < 8; nt++) {
                const __nv_bfloat16* brow = bt + (nt * 8 + g) * AS + 2 * t;
#pragma unroll
                for (int kc = 0; kc < 4; kc++) {
                    uint32_t bb0 = *reinterpret_cast<const uint32_t*>(brow + kc * 16);
                    uint32_t bb1 = *reinterpret_cast<const uint32_t*>(brow + kc * 16 + 8);
                    mma_bf16(acc[nt], &af[kc * 4], bb0, bb1);
                }
            }
        }
        // epilogue: bias + optional relu + store
        const float* bc = bp[c];
        float* oc = op[c];
        bool rl = (relu_mask >> c) & 1;
#pragma unroll
        for (int nt = 0; nt < 8; nt++) {
            int col = nt * 8 + 2 * t;
            float bx = bc ? __ldg(bc + col) : 0.f;
            float by = bc ? __ldg(bc + col + 1) : 0.f;
            float2 v0, v1;
            v0.x = acc[nt][0] + bx; v0.y = acc[nt][1] + by;
            v1.x = acc[nt][2] + bx; v1.y = acc[nt][3] + by;
            if (rl) {
                v0.x = fmaxf(v0.x, 0.f); v0.y = fmaxf(v0.y, 0.f);
                v1.x = fmaxf(v1.x, 0.f); v1.y = fmaxf(v1.y, 0.f);
            }
            if (row0 < R) *reinterpret_cast<float2*>(oc + (size_t)row0 * 64 + col) = v0;
            if (row1 < R) *reinterpret_cast<float2*>(oc + (size_t)row1 * 64 + col) = v1;
        }
    }
}

// ======================= fused gather (elementwise epilogue) ==================
__global__ void __launch_bounds__(256) k_gatherA(float* __restrict__ out) {
    int row = blockIdx.x * 8 + (threadIdx.x >> 5);
    if (row >= NA) return;
    int lane = threadIdx.x & 31;
    int b0 = g_off[row],      e0 = g_off[row + 1];
    int b1 = g_off[NA + row], e1 = g_off[NA + row + 1];
    float s0 = g_zA[(size_t)row * 64 + lane];
    float s1 = g_zA[(size_t)row * 64 + lane + 32];
    int j = b0;
    for (; j + 1 < e0; j += 2) {
        int sa = __ldg(&g_csr[j]), sb = __ldg(&g_csr[j + 1]);
        s0 += g_Taa[(size_t)sa * 64 + lane] + g_Taa[(size_t)sb * 64 + lane];
        s1 += g_Taa[(size_t)sa * 64 + lane + 32] + g_Taa[(size_t)sb * 64 + lane + 32];
    }
    if (j < e0) {
        int sa = __ldg(&g_csr[j]);
        s0 += g_Taa[(size_t)sa * 64 + lane]; s1 += g_Taa[(size_t)sa * 64 + lane + 32];
    }
    j = b1;
    for (; j + 1 < e1; j += 2) {
        int sa = __ldg(&g_csr[j]), sb = __ldg(&g_csr[j + 1]);
        s0 += g_Tba[(size_t)sa * 64 + lane] + g_Tba[(size_t)sb * 64 + lane];
        s1 += g_Tba[(size_t)sa * 64 + lane + 32] + g_Tba[(size_t)sb * 64 + lane + 32];
    }
    if (j < e1) {
        int sa = __ldg(&g_csr[j]);
        s0 += g_Tba[(size_t)sa * 64 + lane]; s1 += g_Tba[(size_t)sa * 64 + lane + 32];
    }
    out[(size_t)row * 64 + lane]      = fmaxf(s0, 0.f);
    out[(size_t)row * 64 + lane + 32] = fmaxf(s1, 0.f);
}

__global__ void __launch_bounds__(256) k_gatherB(float* __restrict__ out) {
    int row = blockIdx.x * 8 + (threadIdx.x >> 5);
    if (row >= NB) return;
    int lane = threadIdx.x & 31;
    int b0 = g_off[2 * NA + row], e0 = g_off[2 * NA + row + 1];
    float s0 = g_zB[(size_t)row * 64 + lane];
    float s1 = g_zB[(size_t)row * 64 + lane + 32];
    int j = b0;
    for (; j + 1 < e0; j += 2) {
        int sa = __ldg(&g_csr[j]), sb = __ldg(&g_csr[j + 1]);
        s0 += g_Tab[(size_t)sa * 64 + lane] + g_Tab[(size_t)sb * 64 + lane];
        s1 += g_Tab[(size_t)sa * 64 + lane + 32] + g_Tab[(size_t)sb * 64 + lane + 32];
    }
    if (j < e0) {
        int sa = __ldg(&g_csr[j]);
        s0 += g_Tab[(size_t)sa * 64 + lane]; s1 += g_Tab[(size_t)sa * 64 + lane + 32];
    }
    out[(size_t)row * 64 + lane]      = fmaxf(s0, 0.f);
    out[(size_t)row * 64 + lane + 32] = fmaxf(s1, 0.f);
}

// ==============================================================================
extern "C" void kernel_launch(void* const* d_in, const int* in_sizes, int n_in,
                              void* d_out, int out_size) {
    const int*   src_aa = (const int*)d_in[0];
    const int*   dst_aa = (const int*)d_in[1];
    const int*   src_ab = (const int*)d_in[2];
    const int*   dst_ab = (const int*)d_in[3];
    const int*   src_ba = (const int*)d_in[4];
    const int*   dst_ba = (const int*)d_in[5];
    const float* embA   = (const float*)d_in[6];
    const float* embB   = (const float*)d_in[7];
    const float* Waa    = (const float*)d_in[8];
    const float* baa    = (const float*)d_in[9];
    const float* Wab    = (const float*)d_in[10];
    const float* bab    = (const float*)d_in[11];
    const float* Wba    = (const float*)d_in[12];
    const float* bba    = (const float*)d_in[13];
    const float* WnA    = (const float*)d_in[14];
    const float* bnA    = (const float*)d_in[15];
    const float* WnB    = (const float*)d_in[16];
    const float* bnB    = (const float*)d_in[17];
    const int Eaa = in_sizes[0];
    const int Eab = in_sizes[2];
    const int Eba = in_sizes[4];
    float* out = (float*)d_out;

    cudaFuncSetAttribute(k_gemm, cudaFuncAttributeMaxDynamicSharedMemorySize, SMEM_GEMM_BYTES);

    void *p_hA, *p_hB, *p_maa, *p_mab, *p_mba, *p_zA, *p_zB, *p_Taa, *p_Tab, *p_Tba;
    cudaGetSymbolAddress(&p_hA, g_hA);
    cudaGetSymbolAddress(&p_hB, g_hB);
    cudaGetSymbolAddress(&p_maa, g_maa);
    cudaGetSymbolAddress(&p_mab, g_mab);
    cudaGetSymbolAddress(&p_mba, g_mba);
    cudaGetSymbolAddress(&p_zA, g_zA);
    cudaGetSymbolAddress(&p_zB, g_zB);
    cudaGetSymbolAddress(&p_Taa, g_Taa);
    cudaGetSymbolAddress(&p_Tab, g_Tab);
    cudaGetSymbolAddress(&p_Tba, g_Tba);

    // layer-1 weight slices (row-major [L, in, out])
    const float* Waa1 = Waa + 64 * 64;
    const float* Wab1 = Wab + 64 * 64;
    const float* Wba1 = Wba + 64 * 64;
    const float* baa1 = baa + 64;
    const float* bab1 = bab + 64;
    const float* bba1 = bba + 64;
    const float* WnA1 = WnA + 192 * 64;          // [192,64]
    const float* WnB1 = WnB + 128 * 64;          // [128,64]
    const float* bnA1 = bnA + 64;
    const float* bnB1 = bnB + 64;

    // 1. CSR build (deg -> scan -> fill); layout [aa->A | ba->A | ab->B]
    k_zero_deg<<<(NTOT + 255) / 256, 256>>>();
    k_deg<<<(Eaa + 255) / 256, 256>>>(dst_aa, Eaa, 0);
    k_deg<<<(Eba + 255) / 256, 256>>>(dst_ba, Eba, NA);
    k_deg<<<(Eab + 255) / 256, 256>>>(dst_ab, Eab, 2 * NA);
    k_scan1<<<NCHUNK, 256>>>();
    k_scan2<<<1, 512>>>();
    k_scan3<<<(NTOT + 255) / 256, 256>>>();
    k_fill<<<(Eaa + 255) / 256, 256>>>(src_aa, dst_aa, Eaa, 0);
    k_fill<<<(Eba + 255) / 256, 256>>>(src_ba, dst_ba, Eba, NA);
    k_fill<<<(Eab + 255) / 256, 256>>>(src_ab, dst_ab, Eab, 2 * NA);

    // 2. layer-0 closed form + node states
    k_small<<<1, 64>>>(embA, embB, Waa, baa, Wab, bab, Wba, bba, WnA, bnA, WnB, bnB);
    k_h<<<((NA + NB) * 16 + 255) / 256, 256>>>();

    // 3. dense phase on tensor cores (mma.sync bf16 hi/lo)
    // G1: hA @ [Waa1 | Wab1 | WnA1.blk0]  -> m_aa (relu), m_ab (relu), zA (+bnA1)
    k_gemm<<<(NA + 127) / 128, 256, SMEM_GEMM_BYTES>>>(
        (const float*)p_hA, NA, Waa1, Wab1, WnA1,
        baa1, bab1, bnA1,
        (float*)p_maa, (float*)p_mab, (float*)p_zA, 3, 0b011);
    // G2: hB @ [Wba1 | WnB1.blk0] -> m_ba (relu +bba1), zB (+bnB1, no relu)
    k_gemm<<<(NB + 127) / 128, 256, SMEM_GEMM_BYTES>>>(
        (const float*)p_hB, NB, Wba1, WnB1, nullptr,
        bba1, bnB1, nullptr,
        (float*)p_mba, (float*)p_zB, nullptr, 2, 0b01);
    // G3: T_aa = m_aa @ WnA1.blk1
    k_gemm<<<(NA + 127) / 128, 256, SMEM_GEMM_BYTES>>>(
        (const float*)p_maa, NA, WnA1 + 64 * 64, nullptr, nullptr,
        nullptr, nullptr, nullptr,
        (float*)p_Taa, nullptr, nullptr, 1, 0);
    // G4: T_ab = m_ab @ WnB1.blk1
    k_gemm<<<(NA + 127) / 128, 256, SMEM_GEMM_BYTES>>>(
        (const float*)p_mab, NA, WnB1 + 64 * 64, nullptr, nullptr,
        nullptr, nullptr, nullptr,
        (float*)p_Tab, nullptr, nullptr, 1, 0);
    // G5: T_ba = m_ba @ WnA1.blk2
    k_gemm<<<(NB + 127) / 128, 256, SMEM_GEMM_BYTES>>>(
        (const float*)p_mba, NB, WnA1 + 128 * 64, nullptr, nullptr,
        nullptr, nullptr, nullptr,
        (float*)p_Tba, nullptr, nullptr, 1, 0);

    // 4. fused gather-sum + relu -> output
    k_gatherA<<<(NA + 7) / 8, 256>>>(out);
    k_gatherB<<<(NB + 7) / 8, 256>>>(out + (size_t)NA * 64);
}

// round 5
// speedup vs baseline: 3.5493x; 1.6962x over previous
#include <cuda_runtime.h>
#include <cuda_bf16.h>
#include <cstdint>

#define NA 100000
#define NB 100000
#define D 64
#define NTOT (NA + NA + NB)                 // deg/off layout: [aa->A | ba->A | ab->B]
#define NCHUNK ((NTOT + 1023) / 1024)
#define ECAP 2000000
#define AS 72                               // smem row stride (bf16), conflict-free

// ======================= scratch =============================================
__device__ int   g_deg[NTOT];
__device__ int   g_off[NTOT + 1];
__device__ int   g_cur[NTOT];
__device__ int   g_csr[ECAP];
__device__ int   g_bsum[NCHUNK];
__device__ int   g_bsumx[NCHUNK];
__device__ float g_vec[5 * D];        // cA, u_aa, u_ba, cB, u_ab
__device__ float g_zA[NA * D];
__device__ float g_zB[NB * D];
__device__ float g_Taa[NA * D];
__device__ float g_Tab[NA * D];
__device__ float g_Tba[NB * D];

// ======================= sparse machinery ====================================
__global__ void k_zero_deg() {
    int i = blockIdx.x * blockDim.x + threadIdx.x;
    if (i < NTOT) g_deg[i] = 0;
}
// one kernel for all three histograms
__global__ void k_deg_all(const int* __restrict__ d_aa, int Eaa,
                          const int* __restrict__ d_ba, int Eba,
                          const int* __restrict__ d_ab, int Eab) {
    int i = blockIdx.x * blockDim.x + threadIdx.x;
    if (i < Eaa) {
        atomicAdd(&g_deg[d_aa[i]], 1);
    } else if (i < Eaa + Eba) {
        atomicAdd(&g_deg[NA + d_ba[i - Eaa]], 1);
    } else if (i < Eaa + Eba + Eab) {
        atomicAdd(&g_deg[2 * NA + d_ab[i - Eaa - Eba]], 1);
    }
}
__global__ void k_scan1() {
    __shared__ int ss[256];
    int t = threadIdx.x;
    int base = blockIdx.x * 1024 + t * 4;
    int v0 = (base + 0 < NTOT) ? g_deg[base + 0] : 0;
    int v1 = (base + 1 < NTOT) ? g_deg[base + 1] : 0;
    int v2 = (base + 2 < NTOT) ? g_deg[base + 2] : 0;
    int v3 = (base + 3 < NTOT) ? g_deg[base + 3] : 0;
    int s = v0 + v1 + v2 + v3;
    ss[t] = s;
    __syncthreads();
    for (int off = 1; off < 256; off <<= 1) {
        int x = (t >= off) ? ss[t - off] : 0;
        __syncthreads();
        ss[t] += x;
        __syncthreads();
    }
    int run = ss[t] - s;
    if (t == 255) g_bsum[blockIdx.x] = ss[255];
    if (base + 0 < NTOT) { g_off[base + 0] = run; run += v0; }
    if (base + 1 < NTOT) { g_off[base + 1] = run; run += v1; }
    if (base + 2 < NTOT) { g_off[base + 2] = run; run += v2; }
    if (base + 3 < NTOT) { g_off[base + 3] = run; }
}
__global__ void k_scan2() {
    __shared__ int ss[512];
    int t = threadIdx.x;
    int orig = (t < NCHUNK) ? g_bsum[t] : 0;
    ss[t] = orig;
    __syncthreads();
    for (int off = 1; off < 512; off <<= 1) {
        int x = (t >= off) ? ss[t - off] : 0;
        __syncthreads();
        ss[t] += x;
        __syncthreads();
    }
    if (t < NCHUNK) g_bsumx[t] = ss[t] - orig;
    if (t == 511) g_off[NTOT] = ss[511];
}
__global__ void k_scan3() {
    int i = blockIdx.x * blockDim.x + threadIdx.x;
    if (i < NTOT) {
        int v = g_off[i] + g_bsumx[i >> 10];
        g_off[i] = v;
        g_cur[i] = v;
    }
}
__global__ void k_fill_all(const int* __restrict__ s_aa, const int* __restrict__ d_aa, int Eaa,
                           const int* __restrict__ s_ba, const int* __restrict__ d_ba, int Eba,
                           const int* __restrict__ s_ab, const int* __restrict__ d_ab, int Eab) {
    int i = blockIdx.x * blockDim.x + threadIdx.x;
    int srcv, base, dstv;
    if (i < Eaa) { srcv = s_aa[i]; dstv = d_aa[i]; base = 0; }
    else if (i < Eaa + Eba) { int j = i - Eaa; srcv = s_ba[j]; dstv = d_ba[j]; base = NA; }
    else if (i < Eaa + Eba + Eab) { int j = i - Eaa - Eba; srcv = s_ab[j]; dstv = d_ab[j]; base = 2 * NA; }
    else return;
    int pos = atomicAdd(&g_cur[base + dstv], 1);
    g_csr[pos] = srcv;
}

// ======================= layer-0 closed form =================================
__global__ void k_small(const float* __restrict__ embA, const float* __restrict__ embB,
                        const float* __restrict__ Waa, const float* __restrict__ baa,
                        const float* __restrict__ Wab, const float* __restrict__ bab,
                        const float* __restrict__ Wba, const float* __restrict__ bba,
                        const float* __restrict__ WnA, const float* __restrict__ bnA,
                        const float* __restrict__ WnB, const float* __restrict__ bnB) {
    __shared__ float sA[D], sB[D], vaa[D], vab[D], vba[D];
    int c = threadIdx.x;
    sA[c] = embA[c]; sB[c] = embB[c];
    __syncthreads();
    float a0 = baa[c], a1 = bab[c], a2 = bba[c];
    for (int k = 0; k < D; k++) {
        a0 += sA[k] * Waa[k * D + c];
        a1 += sA[k] * Wab[k * D + c];
        a2 += sB[k] * Wba[k * D + c];
    }
    vaa[c] = fmaxf(a0, 0.f); vab[c] = fmaxf(a1, 0.f); vba[c] = fmaxf(a2, 0.f);
    __syncthreads();
    float cA = bnA[c], uaa = 0.f, uba = 0.f, cB = bnB[c], uab = 0.f;
    for (int k = 0; k < D; k++) {
        cA  += sA[k]  * WnA[k * D + c];
        uaa += vaa[k] * WnA[(D + k) * D + c];
        uba += vba[k] * WnA[(2 * D + k) * D + c];
        cB  += sB[k]  * WnB[k * D + c];
        uab += vab[k] * WnB[(D + k) * D + c];
    }
    g_vec[c] = cA; g_vec[D + c] = uaa; g_vec[2 * D + c] = uba;
    g_vec[3 * D + c] = cB; g_vec[4 * D + c] = uab;
}

// ======================= MMA helpers =========================================
__device__ __forceinline__ void mma_bf16(float c[4], const uint32_t a[4],
                                         uint32_t b0, uint32_t b1) {
    asm volatile("mma.sync.aligned.m16n8k16.row.col.f32.bf16.bf16.f32 "
                 "{%0,%1,%2,%3}, {%4,%5,%6,%7}, {%8,%9}, {%0,%1,%2,%3};"
                 : "+f"(c[0]), "+f"(c[1]), "+f"(c[2]), "+f"(c[3])
                 : "r"(a[0]), "r"(a[1]), "r"(a[2]), "r"(a[3]), "r"(b0), "r"(b1));
}
__device__ __forceinline__ void pack_hl(float x, float y, uint32_t& hi, uint32_t& lo) {
    __nv_bfloat162 H, L;
    H.x = __float2bfloat16(x); H.y = __float2bfloat16(y);
    L.x = __float2bfloat16(x - __bfloat162float(H.x));
    L.y = __float2bfloat16(y - __bfloat162float(H.y));
    hi = *reinterpret_cast<uint32_t*>(&H);
    lo = *reinterpret_cast<uint32_t*>(&L);
}
// 3-term hi/lo GEMM of one 128x64 tile slice (per-warp 16 rows)
__device__ __forceinline__ void gemm_tile(float acc[8][4],
                                          const uint32_t* Ahi, const uint32_t* Alo,
                                          const __nv_bfloat16* whi, int g, int t) {
    const __nv_bfloat16* wlo = whi + 64 * AS;
#pragma unroll
    for (int nt = 0; nt < 8; nt++) {
        const __nv_bfloat16* bh = whi + (nt * 8 + g) * AS + 2 * t;
        const __nv_bfloat16* bl = wlo + (nt * 8 + g) * AS + 2 * t;
#pragma unroll
        for (int kc = 0; kc < 4; kc++) {
            uint32_t bh0 = *reinterpret_cast<const uint32_t*>(bh + kc * 16);
            uint32_t bh1 = *reinterpret_cast<const uint32_t*>(bh + kc * 16 + 8);
            uint32_t bl0 = *reinterpret_cast<const uint32_t*>(bl + kc * 16);
            uint32_t bl1 = *reinterpret_cast<const uint32_t*>(bl + kc * 16 + 8);
            mma_bf16(acc[nt], &Ahi[kc * 4], bh0, bh1);
            mma_bf16(acc[nt], &Ahi[kc * 4], bl0, bl1);
            mma_bf16(acc[nt], &Alo[kc * 4], bh0, bh1);
        }
    }
}
// C fragments (8 n-tiles) + bias + relu  ->  A fragments for the next GEMM
__device__ __forceinline__ void c2a(float acc[8][4], const float* __restrict__ bias,
                                    uint32_t A2hi[16], uint32_t A2lo[16], int t) {
#pragma unroll
    for (int kc = 0; kc < 4; kc++) {
        int nt0 = 2 * kc, nt1 = nt0 + 1;
        float b00 = __ldg(bias + nt0 * 8 + 2 * t), b01 = __ldg(bias + nt0 * 8 + 2 * t + 1);
        float b10 = __ldg(bias + nt1 * 8 + 2 * t), b11 = __ldg(bias + nt1 * 8 + 2 * t + 1);
        float x0 = fmaxf(acc[nt0][0] + b00, 0.f), x1 = fmaxf(acc[nt0][1] + b01, 0.f);
        float x2 = fmaxf(acc[nt0][2] + b00, 0.f), x3 = fmaxf(acc[nt0][3] + b01, 0.f);
        float y0 = fmaxf(acc[nt1][0] + b10, 0.f), y1 = fmaxf(acc[nt1][1] + b11, 0.f);
        float y2 = fmaxf(acc[nt1][2] + b10, 0.f), y3 = fmaxf(acc[nt1][3] + b11, 0.f);
        pack_hl(x0, x1, A2hi[kc * 4 + 0], A2lo[kc * 4 + 0]);
        pack_hl(x2, x3, A2hi[kc * 4 + 1], A2lo[kc * 4 + 1]);
        pack_hl(y0, y1, A2hi[kc * 4 + 2], A2lo[kc * 4 + 2]);
        pack_hl(y2, y3, A2hi[kc * 4 + 3], A2lo[kc * 4 + 3]);
    }
}
__device__ __forceinline__ void store_tile(float acc[8][4], const float* __restrict__ bias,
                                           float* __restrict__ out, int row0, int row1,
                                           int R, int t) {
#pragma unroll
    for (int nt = 0; nt < 8; nt++) {
        int col = nt * 8 + 2 * t;
        float bx = bias ? __ldg(bias + col) : 0.f;
        float by = bias ? __ldg(bias + col + 1) : 0.f;
        float2 v0 = make_float2(acc[nt][0] + bx, acc[nt][1] + by);
        float2 v1 = make_float2(acc[nt][2] + bx, acc[nt][3] + by);
        if (row0 < R) *reinterpret_cast<float2*>(out + (size_t)row0 * 64 + col) = v0;
        if (row1 < R) *reinterpret_cast<float2*>(out + (size_t)row1 * 64 + col) = v1;
    }
}
__device__ __forceinline__ void stage_w(__nv_bfloat16* sm, const float* const* wsrc,
                                        int nm, int tid) {
    for (int m = 0; m < nm; m++) {
        const float* w = wsrc[m];
        __nv_bfloat16* whi = sm + m * 2 * 64 * AS;
        __nv_bfloat16* wlo = whi + 64 * AS;
        for (int i = tid; i < 4096; i += 256) {
            int k = i >> 6, n = i & 63;
            float x = w[i];
            __nv_bfloat16 hi = __float2bfloat16(x);
            whi[n * AS + k] = hi;
            wlo[n * AS + k] = __float2bfloat16(x - __bfloat162float(hi));
        }
    }
}

// ======================= fused dense kernels ==================================
// A nodes: h from degrees -> {zA, T_aa = relu(h@Waa1+baa1)@WnA1.blk1,
//                                  T_ab = relu(h@Wab1+bab1)@WnB1.blk1}
#define SMEM_A_BYTES (5 * 2 * 64 * AS * 2)   // 92160
__global__ void __launch_bounds__(256) k_gemmA(
        const float* __restrict__ Waa1, const float* __restrict__ baa1,
        const float* __restrict__ Wab1, const float* __restrict__ bab1,
        const float* __restrict__ WnA1, const float* __restrict__ bnA1,
        const float* __restrict__ WnB1blk1) {
    extern __shared__ __nv_bfloat16 sm[];
    int tid = threadIdx.x;
    const float* wsrc[5] = { Waa1, Wab1, WnA1, WnA1 + 4096, WnB1blk1 };
    stage_w(sm, wsrc, 5, tid);
    __syncthreads();

    int lane = tid & 31, wid = tid >> 5;
    int g = lane >> 2, t = lane & 3;
    int row0 = blockIdx.x * 128 + wid * 16 + g, row1 = row0 + 8;
    int r0 = min(row0, NA - 1), r1 = min(row1, NA - 1);
    float d10 = (float)(g_off[r0 + 1] - g_off[r0]);
    float d20 = (float)(g_off[NA + r0 + 1] - g_off[NA + r0]);
    float d11 = (float)(g_off[r1 + 1] - g_off[r1]);
    float d21 = (float)(g_off[NA + r1 + 1] - g_off[NA + r1]);

    // h fragments (computed in-register from the layer-0 closed form)
    uint32_t Ahi[16], Alo[16];
#pragma unroll
    for (int kc = 0; kc < 4; kc++) {
        int c0 = kc * 16 + 2 * t;
#pragma unroll
        for (int half = 0; half < 2; half++) {     // half=0: k 0-7, half=1: k 8-15
            int c = c0 + half * 8;
            float v0 = __ldg(g_vec + c),     u0 = __ldg(g_vec + 64 + c),     w0 = __ldg(g_vec + 128 + c);
            float v1 = __ldg(g_vec + c + 1), u1 = __ldg(g_vec + 64 + c + 1), w1 = __ldg(g_vec + 128 + c + 1);
            float h00 = fmaxf(v0 + d10 * u0 + d20 * w0, 0.f);
            float h01 = fmaxf(v1 + d10 * u1 + d20 * w1, 0.f);
            float h10 = fmaxf(v0 + d11 * u0 + d21 * w0, 0.f);
            float h11 = fmaxf(v1 + d11 * u1 + d21 * w1, 0.f);
            pack_hl(h00, h01, Ahi[kc * 4 + half * 2 + 0], Alo[kc * 4 + half * 2 + 0]);
            pack_hl(h10, h11, Ahi[kc * 4 + half * 2 + 1], Alo[kc * 4 + half * 2 + 1]);
        }
    }

    float acc[8][4], acc2[8][4];
    uint32_t A2hi[16], A2lo[16];

    // zA = h @ WnA1.blk0 + bnA1  (mat 2)
#pragma unroll
    for (int nt = 0; nt < 8; nt++) { acc[nt][0]=0.f; acc[nt][1]=0.f; acc[nt][2]=0.f; acc[nt][3]=0.f; }
    gemm_tile(acc, Ahi, Alo, sm + 2 * 2 * 64 * AS, g, t);
    store_tile(acc, bnA1, g_zA, row0, row1, NA, t);

    // T_aa = relu(h@Waa1 + baa1) @ WnA1.blk1  (mats 0 -> 3)
#pragma unroll
    for (int nt = 0; nt < 8; nt++) { acc[nt][0]=0.f; acc[nt][1]=0.f; acc[nt][2]=0.f; acc[nt][3]=0.f; }
    gemm_tile(acc, Ahi, Alo, sm, g, t);
    c2a(acc, baa1, A2hi, A2lo, t);
#pragma unroll
    for (int nt = 0; nt < 8; nt++) { acc2[nt][0]=0.f; acc2[nt][1]=0.f; acc2[nt][2]=0.f; acc2[nt][3]=0.f; }
    gemm_tile(acc2, A2hi, A2lo, sm + 3 * 2 * 64 * AS, g, t);
    store_tile(acc2, nullptr, g_Taa, row0, row1, NA, t);

    // T_ab = relu(h@Wab1 + bab1) @ WnB1.blk1  (mats 1 -> 4)
#pragma unroll
    for (int nt = 0; nt < 8; nt++) { acc[nt][0]=0.f; acc[nt][1]=0.f; acc[nt][2]=0.f; acc[nt][3]=0.f; }
    gemm_tile(acc, Ahi, Alo, sm + 1 * 2 * 64 * AS, g, t);
    c2a(acc, bab1, A2hi, A2lo, t);
#pragma unroll
    for (int nt = 0; nt < 8; nt++) { acc2[nt][0]=0.f; acc2[nt][1]=0.f; acc2[nt][2]=0.f; acc2[nt][3]=0.f; }
    gemm_tile(acc2, A2hi, A2lo, sm + 4 * 2 * 64 * AS, g, t);
    store_tile(acc2, nullptr, g_Tab, row0, row1, NA, t);
}

// B nodes: h from degrees -> {zB, T_ba = relu(h@Wba1+bba1)@WnA1.blk2}
#define SMEM_B_BYTES (3 * 2 * 64 * AS * 2)   // 55296
__global__ void __launch_bounds__(256) k_gemmB(
        const float* __restrict__ Wba1, const float* __restrict__ bba1,
        const float* __restrict__ WnB1, const float* __restrict__ bnB1,
        const float* __restrict__ WnA1blk2) {
    extern __shared__ __nv_bfloat16 sm[];
    int tid = threadIdx.x;
    const float* wsrc[3] = { Wba1, WnB1, WnA1blk2 };
    stage_w(sm, wsrc, 3, tid);
    __syncthreads();

    int lane = tid & 31, wid = tid >> 5;
    int g = lane >> 2, t = lane & 3;
    int row0 = blockIdx.x * 128 + wid * 16 + g, row1 = row0 + 8;
    int r0 = min(row0, NB - 1), r1 = min(row1, NB - 1);
    float d0 = (float)(g_off[2 * NA + r0 + 1] - g_off[2 * NA + r0]);
    float d1 = (float)(g_off[2 * NA + r1 + 1] - g_off[2 * NA + r1]);

    uint32_t Ahi[16], Alo[16];
#pragma unroll
    for (int kc = 0; kc < 4; kc++) {
        int c0 = kc * 16 + 2 * t;
#pragma unroll
        for (int half = 0; half < 2; half++) {
            int c = c0 + half * 8;
            float v0 = __ldg(g_vec + 192 + c),     u0 = __ldg(g_vec + 256 + c);
            float v1 = __ldg(g_vec + 192 + c + 1), u1 = __ldg(g_vec + 256 + c + 1);
            float h00 = fmaxf(v0 + d0 * u0, 0.f);
            float h01 = fmaxf(v1 + d0 * u1, 0.f);
            float h10 = fmaxf(v0 + d1 * u0, 0.f);
            float h11 = fmaxf(v1 + d1 * u1, 0.f);
            pack_hl(h00, h01, Ahi[kc * 4 + half * 2 + 0], Alo[kc * 4 + half * 2 + 0]);
            pack_hl(h10, h11, Ahi[kc * 4 + half * 2 + 1], Alo[kc * 4 + half * 2 + 1]);
        }
    }

    float acc[8][4], acc2[8][4];
    uint32_t A2hi[16], A2lo[16];

    // zB = h @ WnB1.blk0 + bnB1  (mat 1)
#pragma unroll
    for (int nt = 0; nt < 8; nt++) { acc[nt][0]=0.f; acc[nt][1]=0.f; acc[nt][2]=0.f; acc[nt][3]=0.f; }
    gemm_tile(acc, Ahi, Alo, sm + 1 * 2 * 64 * AS, g, t);
    store_tile(acc, bnB1, g_zB, row0, row1, NB, t);

    // T_ba = relu(h@Wba1 + bba1) @ WnA1.blk2  (mats 0 -> 2)
#pragma unroll
    for (int nt = 0; nt < 8; nt++) { acc[nt][0]=0.f; acc[nt][1]=0.f; acc[nt][2]=0.f; acc[nt][3]=0.f; }
    gemm_tile(acc, Ahi, Alo, sm, g, t);
    c2a(acc, bba1, A2hi, A2lo, t);
#pragma unroll
    for (int nt = 0; nt < 8; nt++) { acc2[nt][0]=0.f; acc2[nt][1]=0.f; acc2[nt][2]=0.f; acc2[nt][3]=0.f; }
    gemm_tile(acc2, A2hi, A2lo, sm + 2 * 2 * 64 * AS, g, t);
    store_tile(acc2, nullptr, g_Tba, row0, row1, NB, t);
}

// ======================= fused gather (one kernel, float2 lanes) ==============
__global__ void __launch_bounds__(256) k_gather(float* __restrict__ out) {
    int row = blockIdx.x * 8 + (threadIdx.x >> 5);
    if (row >= NA + NB) return;
    int lane = threadIdx.x & 31;
    float2 s;
    if (row < NA) {
        s = *reinterpret_cast<const float2*>(g_zA + (size_t)row * 64 + lane * 2);
        int b0 = g_off[row], e0 = g_off[row + 1];
        int b1 = g_off[NA + row], e1 = g_off[NA + row + 1];
        int j = b0;
        for (; j + 1 < e0; j += 2) {
            int sa = __ldg(&g_csr[j]), sb = __ldg(&g_csr[j + 1]);
            float2 p = *reinterpret_cast<const float2*>(g_Taa + (size_t)sa * 64 + lane * 2);
            float2 q = *reinterpret_cast<const float2*>(g_Taa + (size_t)sb * 64 + lane * 2);
            s.x += p.x + q.x; s.y += p.y + q.y;
        }
        if (j < e0) {
            int sa = __ldg(&g_csr[j]);
            float2 p = *reinterpret_cast<const float2*>(g_Taa + (size_t)sa * 64 + lane * 2);
            s.x += p.x; s.y += p.y;
        }
        j = b1;
        for (; j + 1 < e1; j += 2) {
            int sa = __ldg(&g_csr[j]), sb = __ldg(&g_csr[j + 1]);
            float2 p = *reinterpret_cast<const float2*>(g_Tba + (size_t)sa * 64 + lane * 2);
            float2 q = *reinterpret_cast<const float2*>(g_Tba + (size_t)sb * 64 + lane * 2);
            s.x += p.x + q.x; s.y += p.y + q.y;
        }
        if (j < e1) {
            int sa = __ldg(&g_csr[j]);
            float2 p = *reinterpret_cast<const float2*>(g_Tba + (size_t)sa * 64 + lane * 2);
            s.x += p.x; s.y += p.y;
        }
    } else {
        int rb = row - NA;
        s = *reinterpret_cast<const float2*>(g_zB + (size_t)rb * 64 + lane * 2);
        int b0 = g_off[2 * NA + rb], e0 = g_off[2 * NA + rb + 1];
        int j = b0;
        for (; j + 1 < e0; j += 2) {
            int sa = __ldg(&g_csr[j]), sb = __ldg(&g_csr[j + 1]);
            float2 p = *reinterpret_cast<const float2*>(g_Tab + (size_t)sa * 64 + lane * 2);
            float2 q = *reinterpret_cast<const float2*>(g_Tab + (size_t)sb * 64 + lane * 2);
            s.x += p.x + q.x; s.y += p.y + q.y;
        }
        if (j < e0) {
            int sa = __ldg(&g_csr[j]);
            float2 p = *reinterpret_cast<const float2*>(g_Tab + (size_t)sa * 64 + lane * 2);
            s.x += p.x; s.y += p.y;
        }
    }
    s.x = fmaxf(s.x, 0.f); s.y = fmaxf(s.y, 0.f);
    *reinterpret_cast<float2*>(out + (size_t)row * 64 + lane * 2) = s;
}

// ==============================================================================
extern "C" void kernel_launch(void* const* d_in, const int* in_sizes, int n_in,
                              void* d_out, int out_size) {
    const int*   src_aa = (const int*)d_in[0];
    const int*   dst_aa = (const int*)d_in[1];
    const int*   src_ab = (const int*)d_in[2];
    const int*   dst_ab = (const int*)d_in[3];
    const int*   src_ba = (const int*)d_in[4];
    const int*   dst_ba = (const int*)d_in[5];
    const float* embA   = (const float*)d_in[6];
    const float* embB   = (const float*)d_in[7];
    const float* Waa    = (const float*)d_in[8];
    const float* baa    = (const float*)d_in[9];
    const float* Wab    = (const float*)d_in[10];
    const float* bab    = (const float*)d_in[11];
    const float* Wba    = (const float*)d_in[12];
    const float* bba    = (const float*)d_in[13];
    const float* WnA    = (const float*)d_in[14];
    const float* bnA    = (const float*)d_in[15];
    const float* WnB    = (const float*)d_in[16];
    const float* bnB    = (const float*)d_in[17];
    const int Eaa = in_sizes[0];
    const int Eab = in_sizes[2];
    const int Eba = in_sizes[4];
    const int Etot = Eaa + Eba + Eab;
    float* out = (float*)d_out;

    cudaFuncSetAttribute(k_gemmA, cudaFuncAttributeMaxDynamicSharedMemorySize, SMEM_A_BYTES);
    cudaFuncSetAttribute(k_gemmB, cudaFuncAttributeMaxDynamicSharedMemorySize, SMEM_B_BYTES);

    // layer-1 weight slices (row-major [L, in, out])
    const float* Waa1 = Waa + 4096;
    const float* Wab1 = Wab + 4096;
    const float* Wba1 = Wba + 4096;
    const float* baa1 = baa + 64;
    const float* bab1 = bab + 64;
    const float* bba1 = bba + 64;
    const float* WnA1 = WnA + 192 * 64;
    const float* WnB1 = WnB + 128 * 64;
    const float* bnA1 = bnA + 64;
    const float* bnB1 = bnB + 64;

    // 1. CSR build
    k_zero_deg<<<(NTOT + 255) / 256, 256>>>();
    k_deg_all<<<(Etot + 255) / 256, 256>>>(dst_aa, Eaa, dst_ba, Eba, dst_ab, Eab);
    k_scan1<<<NCHUNK, 256>>>();
    k_scan2<<<1, 512>>>();
    k_scan3<<<(NTOT + 255) / 256, 256>>>();
    k_fill_all<<<(Etot + 255) / 256, 256>>>(src_aa, dst_aa, Eaa,
                                            src_ba, dst_ba, Eba,
                                            src_ab, dst_ab, Eab);

    // 2. layer-0 closed-form vectors
    k_small<<<1, 64>>>(embA, embB, Waa, baa, Wab, bab, Wba, bba, WnA, bnA, WnB, bnB);

    // 3. fused dense phase (h in registers, 2-stage chained HMMA)
    k_gemmA<<<(NA + 127) / 128, 256, SMEM_A_BYTES>>>(Waa1, baa1, Wab1, bab1, WnA1, bnA1,
                                                     WnB1 + 4096);
    k_gemmB<<<(NB + 127) / 128, 256, SMEM_B_BYTES>>>(Wba1, bba1, WnB1, bnB1,
                                                     WnA1 + 2 * 4096);

    // 4. fused gather-sum + relu -> output
    k_gather<<<(NA + NB + 7) / 8, 256>>>(out);
}

// round 6
// speedup vs baseline: 6.5987x; 1.8592x over previous
#include <cuda_runtime.h>
#include <cuda_bf16.h>
#include <cstdint>

#define NA 100000
#define NB 100000
#define D 64
#define NTOT (NA + NA + NB)                 // deg/off layout: [aa->A | ba->A | ab->B]
#define NCHUNK ((NTOT + 1023) / 1024)
#define ECAP 2000000
#define AS 72                               // smem row stride (bf16), conflict-free
#define CGRID 4096                          // 64x64 degree-pair grid (A); 1-D for B
#define TROWSA (CGRID + NA)
#define TROWSB (CGRID + NB)

// ======================= scratch =============================================
__device__ int   g_deg[NTOT];
__device__ int   g_off[NTOT + 1];
__device__ int   g_cur[NTOT];
__device__ int   g_csr[ECAP];
__device__ int   g_bsum[NCHUNK];
__device__ int   g_bsumx[NCHUNK];
__device__ int   g_novf[2];                 // overflow counters (A, B)
__device__ int   g_cidA[NA];
__device__ int   g_cidB[NB];
__device__ int2  g_ovfA[NA];
__device__ int   g_ovfB[NB];
__device__ float g_TzA[TROWSA * D];
__device__ float g_Taa[TROWSA * D];
__device__ float g_Tab[TROWSA * D];
__device__ float g_TzB[TROWSB * D];
__device__ float g_Tba[TROWSB * D];

// ======================= sparse machinery ====================================
__global__ void k_deg_all(const int* __restrict__ d_aa, int Eaa,
                          const int* __restrict__ d_ba, int Eba,
                          const int* __restrict__ d_ab, int Eab) {
    int i = blockIdx.x * blockDim.x + threadIdx.x;
    if (i < Eaa) {
        atomicAdd(&g_deg[d_aa[i]], 1);
    } else if (i < Eaa + Eba) {
        atomicAdd(&g_deg[NA + d_ba[i - Eaa]], 1);
    } else if (i < Eaa + Eba + Eab) {
        atomicAdd(&g_deg[2 * NA + d_ab[i - Eaa - Eba]], 1);
    }
}
__global__ void k_scan1() {
    __shared__ int ss[256];
    int t = threadIdx.x;
    int base = blockIdx.x * 1024 + t * 4;
    int v0 = (base + 0 < NTOT) ? g_deg[base + 0] : 0;
    int v1 = (base + 1 < NTOT) ? g_deg[base + 1] : 0;
    int v2 = (base + 2 < NTOT) ? g_deg[base + 2] : 0;
    int v3 = (base + 3 < NTOT) ? g_deg[base + 3] : 0;
    int s = v0 + v1 + v2 + v3;
    ss[t] = s;
    __syncthreads();
    for (int off = 1; off < 256; off <<= 1) {
        int x = (t >= off) ? ss[t - off] : 0;
        __syncthreads();
        ss[t] += x;
        __syncthreads();
    }
    int run = ss[t] - s;
    if (t == 255) g_bsum[blockIdx.x] = ss[255];
    if (base + 0 < NTOT) { g_off[base + 0] = run; run += v0; }
    if (base + 1 < NTOT) { g_off[base + 1] = run; run += v1; }
    if (base + 2 < NTOT) { g_off[base + 2] = run; run += v2; }
    if (base + 3 < NTOT) { g_off[base + 3] = run; }
}
__global__ void k_scan2() {
    __shared__ int ss[512];
    int t = threadIdx.x;
    int orig = (t < NCHUNK) ? g_bsum[t] : 0;
    ss[t] = orig;
    __syncthreads();
    for (int off = 1; off < 512; off <<= 1) {
        int x = (t >= off) ? ss[t - off] : 0;
        __syncthreads();
        ss[t] += x;
        __syncthreads();
    }
    if (t < NCHUNK) g_bsumx[t] = ss[t] - orig;
    if (t == 511) g_off[NTOT] = ss[511];
}
// scan fixup + combo-id assignment in one pass
__global__ void k_scan3_cid() {
    int i = blockIdx.x * blockDim.x + threadIdx.x;
    if (i < NTOT) {
        int v = g_off[i] + g_bsumx[i >> 10];
        g_off[i] = v;
        g_cur[i] = v;
    }
    if (i < NA) {
        int d1 = g_deg[i], d2 = g_deg[NA + i];
        int cid;
        if (d1 < 64 && d2 < 64) cid = d1 * 64 + d2;
        else {
            int o = atomicAdd(&g_novf[0], 1);
            g_ovfA[o] = make_int2(d1, d2);
            cid = CGRID + o;
        }
        g_cidA[i] = cid;
    } else if (i < NA + NB) {
        int b = i - NA;
        int d = g_deg[2 * NA + b];
        int cid;
        if (d < CGRID) cid = d;
        else {
            int o = atomicAdd(&g_novf[1], 1);
            g_ovfB[o] = d;
            cid = CGRID + o;
        }
        g_cidB[b] = cid;
    }
}
__global__ void k_fill_all(const int* __restrict__ s_aa, const int* __restrict__ d_aa, int Eaa,
                           const int* __restrict__ s_ba, const int* __restrict__ d_ba, int Eba,
                           const int* __restrict__ s_ab, const int* __restrict__ d_ab, int Eab) {
    int i = blockIdx.x * blockDim.x + threadIdx.x;
    int srcv, base, dstv;
    if (i < Eaa) { srcv = s_aa[i]; dstv = d_aa[i]; base = 0; }
    else if (i < Eaa + Eba) { int j = i - Eaa; srcv = s_ba[j]; dstv = d_ba[j]; base = NA; }
    else if (i < Eaa + Eba + Eab) { int j = i - Eaa - Eba; srcv = s_ab[j]; dstv = d_ab[j]; base = 2 * NA; }
    else return;
    int pos = atomicAdd(&g_cur[base + dstv], 1);
    g_csr[pos] = srcv;
}

// ======================= MMA helpers =========================================
__device__ __forceinline__ void mma_bf16(float c[4], const uint32_t a[4],
                                         uint32_t b0, uint32_t b1) {
    asm volatile("mma.sync.aligned.m16n8k16.row.col.f32.bf16.bf16.f32 "
                 "{%0,%1,%2,%3}, {%4,%5,%6,%7}, {%8,%9}, {%0,%1,%2,%3};"
                 : "+f"(c[0]), "+f"(c[1]), "+f"(c[2]), "+f"(c[3])
                 : "r"(a[0]), "r"(a[1]), "r"(a[2]), "r"(a[3]), "r"(b0), "r"(b1));
}
__device__ __forceinline__ void pack_hl(float x, float y, uint32_t& hi, uint32_t& lo) {
    __nv_bfloat162 H, L;
    H.x = __float2bfloat16(x); H.y = __float2bfloat16(y);
    L.x = __float2bfloat16(x - __bfloat162float(H.x));
    L.y = __float2bfloat16(y - __bfloat162float(H.y));
    hi = *reinterpret_cast<uint32_t*>(&H);
    lo = *reinterpret_cast<uint32_t*>(&L);
}
__device__ __forceinline__ void gemm_tile(float acc[8][4],
                                          const uint32_t* Ahi, const uint32_t* Alo,
                                          const __nv_bfloat16* whi, int g, int t) {
    const __nv_bfloat16* wlo = whi + 64 * AS;
#pragma unroll
    for (int nt = 0; nt < 8; nt++) {
        const __nv_bfloat16* bh = whi + (nt * 8 + g) * AS + 2 * t;
        const __nv_bfloat16* bl = wlo + (nt * 8 + g) * AS + 2 * t;
#pragma unroll
        for (int kc = 0; kc < 4; kc++) {
            uint32_t bh0 = *reinterpret_cast<const uint32_t*>(bh + kc * 16);
            uint32_t bh1 = *reinterpret_cast<const uint32_t*>(bh + kc * 16 + 8);
            uint32_t bl0 = *reinterpret_cast<const uint32_t*>(bl + kc * 16);
            uint32_t bl1 = *reinterpret_cast<const uint32_t*>(bl + kc * 16 + 8);
            mma_bf16(acc[nt], &Ahi[kc * 4], bh0, bh1);
            mma_bf16(acc[nt], &Ahi[kc * 4], bl0, bl1);
            mma_bf16(acc[nt], &Alo[kc * 4], bh0, bh1);
        }
    }
}
__device__ __forceinline__ void c2a(float acc[8][4], const float* __restrict__ bias,
                                    uint32_t A2hi[16], uint32_t A2lo[16], int t) {
#pragma unroll
    for (int kc = 0; kc < 4; kc++) {
        int nt0 = 2 * kc, nt1 = nt0 + 1;
        float b00 = __ldg(bias + nt0 * 8 + 2 * t), b01 = __ldg(bias + nt0 * 8 + 2 * t + 1);
        float b10 = __ldg(bias + nt1 * 8 + 2 * t), b11 = __ldg(bias + nt1 * 8 + 2 * t + 1);
        float x0 = fmaxf(acc[nt0][0] + b00, 0.f), x1 = fmaxf(acc[nt0][1] + b01, 0.f);
        float x2 = fmaxf(acc[nt0][2] + b00, 0.f), x3 = fmaxf(acc[nt0][3] + b01, 0.f);
        float y0 = fmaxf(acc[nt1][0] + b10, 0.f), y1 = fmaxf(acc[nt1][1] + b11, 0.f);
        float y2 = fmaxf(acc[nt1][2] + b10, 0.f), y3 = fmaxf(acc[nt1][3] + b11, 0.f);
        pack_hl(x0, x1, A2hi[kc * 4 + 0], A2lo[kc * 4 + 0]);
        pack_hl(x2, x3, A2hi[kc * 4 + 1], A2lo[kc * 4 + 1]);
        pack_hl(y0, y1, A2hi[kc * 4 + 2], A2lo[kc * 4 + 2]);
        pack_hl(y2, y3, A2hi[kc * 4 + 3], A2lo[kc * 4 + 3]);
    }
}
__device__ __forceinline__ void store_tile(float acc[8][4], const float* __restrict__ bias,
                                           float* __restrict__ out, int row0, int row1,
                                           int R, int t) {
#pragma unroll
    for (int nt = 0; nt < 8; nt++) {
        int col = nt * 8 + 2 * t;
        float bx = bias ? __ldg(bias + col) : 0.f;
        float by = bias ? __ldg(bias + col + 1) : 0.f;
        float2 v0 = make_float2(acc[nt][0] + bx, acc[nt][1] + by);
        float2 v1 = make_float2(acc[nt][2] + bx, acc[nt][3] + by);
        if (row0 < R) *reinterpret_cast<float2*>(out + (size_t)row0 * 64 + col) = v0;
        if (row1 < R) *reinterpret_cast<float2*>(out + (size_t)row1 * 64 + col) = v1;
    }
}
__device__ __forceinline__ void stage_w(__nv_bfloat16* sm, const float* const* wsrc,
                                        int nm, int tid) {
    for (int m = 0; m < nm; m++) {
        const float* w = wsrc[m];
        __nv_bfloat16* whi = sm + m * 2 * 64 * AS;
        __nv_bfloat16* wlo = whi + 64 * AS;
        for (int i = tid; i < 4096; i += 256) {
            int k = i >> 6, n = i & 63;
            float x = w[i];
            __nv_bfloat16 hi = __float2bfloat16(x);
            whi[n * AS + k] = hi;
            wlo[n * AS + k] = __float2bfloat16(x - __bfloat162float(hi));
        }
    }
}

// ======================= combo-table GEMM kernels =============================
// A cells: (d1,d2) -> {TzA, Taa = relu(h@Waa1+baa1)@WnA1.blk1, Tab = relu(h@Wab1+bab1)@WnB1.blk1}
#define SMEM_A_BYTES (5 * 2 * 64 * AS * 2)   // 92160
__global__ void __launch_bounds__(256) k_gemmA(
        const float* __restrict__ embA, const float* __restrict__ embB,
        const float* __restrict__ Waa0, const float* __restrict__ baa0,
        const float* __restrict__ Wba0, const float* __restrict__ bba0,
        const float* __restrict__ WnA0, const float* __restrict__ bnA0,
        const float* __restrict__ Waa1, const float* __restrict__ baa1,
        const float* __restrict__ Wab1, const float* __restrict__ bab1,
        const float* __restrict__ WnA1, const float* __restrict__ bnA1,
        const float* __restrict__ WnB1blk1) {
    int limit = CGRID + g_novf[0];
    if ((int)blockIdx.x * 128 >= limit) return;

    extern __shared__ __nv_bfloat16 sm[];
    __shared__ float sA[64], sB[64], v1[64], v2[64], sv[192];
    int tid = threadIdx.x;
    const float* wsrc[5] = { Waa1, Wab1, WnA1, WnA1 + 4096, WnB1blk1 };
    stage_w(sm, wsrc, 5, tid);
    if (tid < 64) { sA[tid] = embA[tid]; sB[tid] = embB[tid]; }
    __syncthreads();
    if (tid < 64) {
        int c = tid;
        float a0 = baa0[c], a2 = bba0[c];
        for (int k = 0; k < 64; k++) {
            a0 += sA[k] * Waa0[k * 64 + c];
            a2 += sB[k] * Wba0[k * 64 + c];
        }
        v1[c] = fmaxf(a0, 0.f); v2[c] = fmaxf(a2, 0.f);
    }
    __syncthreads();
    if (tid < 64) {
        int c = tid;
        float cA = bnA0[c], uaa = 0.f, uba = 0.f;
        for (int k = 0; k < 64; k++) {
            cA  += sA[k] * WnA0[k * 64 + c];
            uaa += v1[k] * WnA0[(64 + k) * 64 + c];
            uba += v2[k] * WnA0[(128 + k) * 64 + c];
        }
        sv[c] = cA; sv[64 + c] = uaa; sv[128 + c] = uba;
    }
    __syncthreads();

    int lane = tid & 31, wid = tid >> 5;
    int g = lane >> 2, t = lane & 3;
    int row0 = blockIdx.x * 128 + wid * 16 + g, row1 = row0 + 8;
    int r0 = min(row0, limit - 1), r1 = min(row1, limit - 1);
    float d10, d20, d11, d21;
    if (r0 < CGRID) { d10 = (float)(r0 >> 6); d20 = (float)(r0 & 63); }
    else { int2 dd = g_ovfA[r0 - CGRID]; d10 = (float)dd.x; d20 = (float)dd.y; }
    if (r1 < CGRID) { d11 = (float)(r1 >> 6); d21 = (float)(r1 & 63); }
    else { int2 dd = g_ovfA[r1 - CGRID]; d11 = (float)dd.x; d21 = (float)dd.y; }

    uint32_t Ahi[16], Alo[16];
#pragma unroll
    for (int kc = 0; kc < 4; kc++) {
        int c0 = kc * 16 + 2 * t;
#pragma unroll
        for (int half = 0; half < 2; half++) {
            int c = c0 + half * 8;
            float p0 = sv[c],     u0 = sv[64 + c],     w0 = sv[128 + c];
            float p1 = sv[c + 1], u1 = sv[64 + c + 1], w1 = sv[128 + c + 1];
            float h00 = fmaxf(p0 + d10 * u0 + d20 * w0, 0.f);
            float h01 = fmaxf(p1 + d10 * u1 + d20 * w1, 0.f);
            float h10 = fmaxf(p0 + d11 * u0 + d21 * w0, 0.f);
            float h11 = fmaxf(p1 + d11 * u1 + d21 * w1, 0.f);
            pack_hl(h00, h01, Ahi[kc * 4 + half * 2 + 0], Alo[kc * 4 + half * 2 + 0]);
            pack_hl(h10, h11, Ahi[kc * 4 + half * 2 + 1], Alo[kc * 4 + half * 2 + 1]);
        }
    }

    float acc[8][4], acc2[8][4];
    uint32_t A2hi[16], A2lo[16];

    // TzA = h @ WnA1.blk0 + bnA1  (mat 2)
#pragma unroll
    for (int nt = 0; nt < 8; nt++) { acc[nt][0]=0.f; acc[nt][1]=0.f; acc[nt][2]=0.f; acc[nt][3]=0.f; }
    gemm_tile(acc, Ahi, Alo, sm + 2 * 2 * 64 * AS, g, t);
    store_tile(acc, bnA1, g_TzA, row0, row1, limit, t);

    // Taa = relu(h@Waa1 + baa1) @ WnA1.blk1  (mats 0 -> 3)
#pragma unroll
    for (int nt = 0; nt < 8; nt++) { acc[nt][0]=0.f; acc[nt][1]=0.f; acc[nt][2]=0.f; acc[nt][3]=0.f; }
    gemm_tile(acc, Ahi, Alo, sm, g, t);
    c2a(acc, baa1, A2hi, A2lo, t);
#pragma unroll
    for (int nt = 0; nt < 8; nt++) { acc2[nt][0]=0.f; acc2[nt][1]=0.f; acc2[nt][2]=0.f; acc2[nt][3]=0.f; }
    gemm_tile(acc2, A2hi, A2lo, sm + 3 * 2 * 64 * AS, g, t);
    store_tile(acc2, nullptr, g_Taa, row0, row1, limit, t);

    // Tab = relu(h@Wab1 + bab1) @ WnB1.blk1  (mats 1 -> 4)
#pragma unroll
    for (int nt = 0; nt < 8; nt++) { acc[nt][0]=0.f; acc[nt][1]=0.f; acc[nt][2]=0.f; acc[nt][3]=0.f; }
    gemm_tile(acc, Ahi, Alo, sm + 1 * 2 * 64 * AS, g, t);
    c2a(acc, bab1, A2hi, A2lo, t);
#pragma unroll
    for (int nt = 0; nt < 8; nt++) { acc2[nt][0]=0.f; acc2[nt][1]=0.f; acc2[nt][2]=0.f; acc2[nt][3]=0.f; }
    gemm_tile(acc2, A2hi, A2lo, sm + 4 * 2 * 64 * AS, g, t);
    store_tile(acc2, nullptr, g_Tab, row0, row1, limit, t);
}

// B cells: d -> {TzB, Tba = relu(h@Wba1+bba1)@WnA1.blk2}
#define SMEM_B_BYTES (3 * 2 * 64 * AS * 2)   // 55296
__global__ void __launch_bounds__(256) k_gemmB(
        const float* __restrict__ embA, const float* __restrict__ embB,
        const float* __restrict__ Wab0, const float* __restrict__ bab0,
        const float* __restrict__ WnB0, const float* __restrict__ bnB0,
        const float* __restrict__ Wba1, const float* __restrict__ bba1,
        const float* __restrict__ WnB1, const float* __restrict__ bnB1,
        const float* __restrict__ WnA1blk2) {
    int limit = CGRID + g_novf[1];
    if ((int)blockIdx.x * 128 >= limit) return;

    extern __shared__ __nv_bfloat16 sm[];
    __shared__ float sA[64], sB[64], v1[64], sv[128];
    int tid = threadIdx.x;
    const float* wsrc[3] = { Wba1, WnB1, WnA1blk2 };
    stage_w(sm, wsrc, 3, tid);
    if (tid < 64) { sA[tid] = embA[tid]; sB[tid] = embB[tid]; }
    __syncthreads();
    if (tid < 64) {
        int c = tid;
        float a1 = bab0[c];
        for (int k = 0; k < 64; k++) a1 += sA[k] * Wab0[k * 64 + c];
        v1[c] = fmaxf(a1, 0.f);
    }
    __syncthreads();
    if (tid < 64) {
        int c = tid;
        float cB = bnB0[c], uab = 0.f;
        for (int k = 0; k < 64; k++) {
            cB  += sB[k] * WnB0[k * 64 + c];
            uab += v1[k] * WnB0[(64 + k) * 64 + c];
        }
        sv[c] = cB; sv[64 + c] = uab;
    }
    __syncthreads();

    int lane = tid & 31, wid = tid >> 5;
    int g = lane >> 2, t = lane & 3;
    int row0 = blockIdx.x * 128 + wid * 16 + g, row1 = row0 + 8;
    int r0 = min(row0, limit - 1), r1 = min(row1, limit - 1);
    float d0 = (r0 < CGRID) ? (float)r0 : (float)g_ovfB[r0 - CGRID];
    float d1 = (r1 < CGRID) ? (float)r1 : (float)g_ovfB[r1 - CGRID];

    uint32_t Ahi[16], Alo[16];
#pragma unroll
    for (int kc = 0; kc < 4; kc++) {
        int c0 = kc * 16 + 2 * t;
#pragma unroll
        for (int half = 0; half < 2; half++) {
            int c = c0 + half * 8;
            float p0 = sv[c],     u0 = sv[64 + c];
            float p1 = sv[c + 1], u1 = sv[64 + c + 1];
            float h00 = fmaxf(p0 + d0 * u0, 0.f);
            float h01 = fmaxf(p1 + d0 * u1, 0.f);
            float h10 = fmaxf(p0 + d1 * u0, 0.f);
            float h11 = fmaxf(p1 + d1 * u1, 0.f);
            pack_hl(h00, h01, Ahi[kc * 4 + half * 2 + 0], Alo[kc * 4 + half * 2 + 0]);
            pack_hl(h10, h11, Ahi[kc * 4 + half * 2 + 1], Alo[kc * 4 + half * 2 + 1]);
        }
    }

    float acc[8][4], acc2[8][4];
    uint32_t A2hi[16], A2lo[16];

    // TzB = h @ WnB1.blk0 + bnB1  (mat 1)
#pragma unroll
    for (int nt = 0; nt < 8; nt++) { acc[nt][0]=0.f; acc[nt][1]=0.f; acc[nt][2]=0.f; acc[nt][3]=0.f; }
    gemm_tile(acc, Ahi, Alo, sm + 1 * 2 * 64 * AS, g, t);
    store_tile(acc, bnB1, g_TzB, row0, row1, limit, t);

    // Tba = relu(h@Wba1 + bba1) @ WnA1.blk2  (mats 0 -> 2)
#pragma unroll
    for (int nt = 0; nt < 8; nt++) { acc[nt][0]=0.f; acc[nt][1]=0.f; acc[nt][2]=0.f; acc[nt][3]=0.f; }
    gemm_tile(acc, Ahi, Alo, sm, g, t);
    c2a(acc, bba1, A2hi, A2lo, t);
#pragma unroll
    for (int nt = 0; nt < 8; nt++) { acc2[nt][0]=0.f; acc2[nt][1]=0.f; acc2[nt][2]=0.f; acc2[nt][3]=0.f; }
    gemm_tile(acc2, A2hi, A2lo, sm + 2 * 2 * 64 * AS, g, t);
    store_tile(acc2, nullptr, g_Tba, row0, row1, limit, t);
}

// ======================= fused gather (combo tables, hot in L1) ===============
__global__ void __launch_bounds__(256) k_gather(float* __restrict__ out) {
    int row = blockIdx.x * 8 + (threadIdx.x >> 5);
    if (row >= NA + NB) return;
    int lane = threadIdx.x & 31;
    float2 s;
    if (row < NA) {
        int cself = __ldg(&g_cidA[row]);
        s = *reinterpret_cast<const float2*>(g_TzA + (size_t)cself * 64 + lane * 2);
        int b0 = g_off[row], e0 = g_off[row + 1];
        int b1 = g_off[NA + row], e1 = g_off[NA + row + 1];
        int j = b0;
        for (; j + 1 < e0; j += 2) {
            int ca = __ldg(&g_cidA[__ldg(&g_csr[j])]);
            int cb = __ldg(&g_cidA[__ldg(&g_csr[j + 1])]);
            float2 p = *reinterpret_cast<const float2*>(g_Taa + (size_t)ca * 64 + lane * 2);
            float2 q = *reinterpret_cast<const float2*>(g_Taa + (size_t)cb * 64 + lane * 2);
            s.x += p.x + q.x; s.y += p.y + q.y;
        }
        if (j < e0) {
            int ca = __ldg(&g_cidA[__ldg(&g_csr[j])]);
            float2 p = *reinterpret_cast<const float2*>(g_Taa + (size_t)ca * 64 + lane * 2);
            s.x += p.x; s.y += p.y;
        }
        j = b1;
        for (; j + 1 < e1; j += 2) {
            int ca = __ldg(&g_cidB[__ldg(&g_csr[j])]);
            int cb = __ldg(&g_cidB[__ldg(&g_csr[j + 1])]);
            float2 p = *reinterpret_cast<const float2*>(g_Tba + (size_t)ca * 64 + lane * 2);
            float2 q = *reinterpret_cast<const float2*>(g_Tba + (size_t)cb * 64 + lane * 2);
            s.x += p.x + q.x; s.y += p.y + q.y;
        }
        if (j < e1) {
            int ca = __ldg(&g_cidB[__ldg(&g_csr[j])]);
            float2 p = *reinterpret_cast<const float2*>(g_Tba + (size_t)ca * 64 + lane * 2);
            s.x += p.x; s.y += p.y;
        }
    } else {
        int rb = row - NA;
        int cself = __ldg(&g_cidB[rb]);
        s = *reinterpret_cast<const float2*>(g_TzB + (size_t)cself * 64 + lane * 2);
        int b0 = g_off[2 * NA + rb], e0 = g_off[2 * NA + rb + 1];
        int j = b0;
        for (; j + 1 < e0; j += 2) {
            int ca = __ldg(&g_cidA[__ldg(&g_csr[j])]);
            int cb = __ldg(&g_cidA[__ldg(&g_csr[j + 1])]);
            float2 p = *reinterpret_cast<const float2*>(g_Tab + (size_t)ca * 64 + lane * 2);
            float2 q = *reinterpret_cast<const float2*>(g_Tab + (size_t)cb * 64 + lane * 2);
            s.x += p.x + q.x; s.y += p.y + q.y;
        }
        if (j < e0) {
            int ca = __ldg(&g_cidA[__ldg(&g_csr[j])]);
            float2 p = *reinterpret_cast<const float2*>(g_Tab + (size_t)ca * 64 + lane * 2);
            s.x += p.x; s.y += p.y;
        }
    }
    s.x = fmaxf(s.x, 0.f); s.y = fmaxf(s.y, 0.f);
    *reinterpret_cast<float2*>(out + (size_t)row * 64 + lane * 2) = s;
}

// ==============================================================================
extern "C" void kernel_launch(void* const* d_in, const int* in_sizes, int n_in,
                              void* d_out, int out_size) {
    const int*   src_aa = (const int*)d_in[0];
    const int*   dst_aa = (const int*)d_in[1];
    const int*   src_ab = (const int*)d_in[2];
    const int*   dst_ab = (const int*)d_in[3];
    const int*   src_ba = (const int*)d_in[4];
    const int*   dst_ba = (const int*)d_in[5];
    const float* embA   = (const float*)d_in[6];
    const float* embB   = (const float*)d_in[7];
    const float* Waa    = (const float*)d_in[8];
    const float* baa    = (const float*)d_in[9];
    const float* Wab    = (const float*)d_in[10];
    const float* bab    = (const float*)d_in[11];
    const float* Wba    = (const float*)d_in[12];
    const float* bba    = (const float*)d_in[13];
    const float* WnA    = (const float*)d_in[14];
    const float* bnA    = (const float*)d_in[15];
    const float* WnB    = (const float*)d_in[16];
    const float* bnB    = (const float*)d_in[17];
    const int Eaa = in_sizes[0];
    const int Eab = in_sizes[2];
    const int Eba = in_sizes[4];
    const int Etot = Eaa + Eba + Eab;
    float* out = (float*)d_out;

    cudaFuncSetAttribute(k_gemmA, cudaFuncAttributeMaxDynamicSharedMemorySize, SMEM_A_BYTES);
    cudaFuncSetAttribute(k_gemmB, cudaFuncAttributeMaxDynamicSharedMemorySize, SMEM_B_BYTES);

    // layer-1 weight slices (row-major [L, in, out])
    const float* Waa1 = Waa + 4096;
    const float* Wab1 = Wab + 4096;
    const float* Wba1 = Wba + 4096;
    const float* baa1 = baa + 64;
    const float* bab1 = bab + 64;
    const float* bba1 = bba + 64;
    const float* WnA1 = WnA + 192 * 64;
    const float* WnB1 = WnB + 128 * 64;
    const float* bnA1 = bnA + 64;
    const float* bnB1 = bnB + 64;

    void *p_deg, *p_novf;
    cudaGetSymbolAddress(&p_deg, g_deg);
    cudaGetSymbolAddress(&p_novf, g_novf);

    // 1. zero degree histograms + overflow counters
    cudaMemsetAsync(p_deg, 0, sizeof(int) * NTOT);
    cudaMemsetAsync(p_novf, 0, sizeof(int) * 2);

    // 2. CSR build + combo-id assignment
    k_deg_all<<<(Etot + 255) / 256, 256>>>(dst_aa, Eaa, dst_ba, Eba, dst_ab, Eab);
    k_scan1<<<NCHUNK, 256>>>();
    k_scan2<<<1, 512>>>();
    k_scan3_cid<<<(NTOT + 255) / 256, 256>>>();

    // 3. combo tables on tensor cores (before fill; independent of it)
    k_gemmA<<<(CGRID + NA + 127) / 128, 256, SMEM_A_BYTES>>>(
        embA, embB, Waa, baa, Wba, bba, WnA, bnA,
        Waa1, baa1, Wab1, bab1, WnA1, bnA1, WnB1 + 4096);
    k_gemmB<<<(CGRID + NB + 127) / 128, 256, SMEM_B_BYTES>>>(
        embA, embB, Wab, bab, WnB, bnB,
        Wba1, bba1, WnB1, bnB1, WnA1 + 2 * 4096);

    // 4. counting-sort fill
    k_fill_all<<<(Etot + 255) / 256, 256>>>(src_aa, dst_aa, Eaa,
                                            src_ba, dst_ba, Eba,
                                            src_ab, dst_ab, Eab);

    // 5. fused gather-sum + relu -> output
    k_gather<<<(NA + NB + 7) / 8, 256>>>(out);
}

// round 7
// speedup vs baseline: 6.9161x; 1.0481x over previous
#include <cuda_runtime.h>
#include <cuda_bf16.h>
#include <cstdint>

#define NA 100000
#define NB 100000
#define D 64
#define NTOT (NA + NA + NB)                 // deg/off layout: [aa->A | ba->A | ab->B]
#define NCHUNK ((NTOT + 1023) / 1024)
#define ECAP 2000000
#define AS 72                               // smem row stride (bf16), conflict-free
#define CGRID 4096                          // 64x64 degree-pair grid (A); 1-D for B
#define TROWSA (CGRID + NA)
#define TROWSB (CGRID + NB)

// ======================= scratch =============================================
__device__ int   g_deg[NTOT];
__device__ int   g_off[NTOT + 1];
__device__ int   g_cur[NTOT];
__device__ int   g_csr[ECAP];               // stores combo-id of src, grouped by dst
__device__ int   g_bsum[NCHUNK];
__device__ int   g_bsumx[NCHUNK];
__device__ int   g_novf[2];                 // overflow counters (A, B)
__device__ int   g_cidA[NA];
__device__ int   g_cidB[NB];
__device__ int2  g_ovfA[NA];
__device__ int   g_ovfB[NB];
__device__ float g_TzA[TROWSA * D];
__device__ float g_Taa[TROWSA * D];
__device__ float g_Tab[TROWSA * D];
__device__ float g_TzB[TROWSB * D];
__device__ float g_Tba[TROWSB * D];

// ======================= sparse machinery ====================================
__global__ void k_deg_all(const int* __restrict__ d_aa, int Eaa,
                          const int* __restrict__ d_ba, int Eba,
                          const int* __restrict__ d_ab, int Eab) {
    int i = blockIdx.x * blockDim.x + threadIdx.x;
    if (i < Eaa) {
        atomicAdd(&g_deg[d_aa[i]], 1);
    } else if (i < Eaa + Eba) {
        atomicAdd(&g_deg[NA + d_ba[i - Eaa]], 1);
    } else if (i < Eaa + Eba + Eab) {
        atomicAdd(&g_deg[2 * NA + d_ab[i - Eaa - Eba]], 1);
    }
}
__global__ void k_scan1() {
    __shared__ int ss[256];
    int t = threadIdx.x;
    int base = blockIdx.x * 1024 + t * 4;
    int v0 = (base + 0 < NTOT) ? g_deg[base + 0] : 0;
    int v1 = (base + 1 < NTOT) ? g_deg[base + 1] : 0;
    int v2 = (base + 2 < NTOT) ? g_deg[base + 2] : 0;
    int v3 = (base + 3 < NTOT) ? g_deg[base + 3] : 0;
    int s = v0 + v1 + v2 + v3;
    ss[t] = s;
    __syncthreads();
    for (int off = 1; off < 256; off <<= 1) {
        int x = (t >= off) ? ss[t - off] : 0;
        __syncthreads();
        ss[t] += x;
        __syncthreads();
    }
    int run = ss[t] - s;
    if (t == 255) g_bsum[blockIdx.x] = ss[255];
    if (base + 0 < NTOT) { g_off[base + 0] = run; run += v0; }
    if (base + 1 < NTOT) { g_off[base + 1] = run; run += v1; }
    if (base + 2 < NTOT) { g_off[base + 2] = run; run += v2; }
    if (base + 3 < NTOT) { g_off[base + 3] = run; }
}
__global__ void k_scan2() {
    __shared__ int ss[512];
    int t = threadIdx.x;
    int orig = (t < NCHUNK) ? g_bsum[t] : 0;
    ss[t] = orig;
    __syncthreads();
    for (int off = 1; off < 512; off <<= 1) {
        int x = (t >= off) ? ss[t - off] : 0;
        __syncthreads();
        ss[t] += x;
        __syncthreads();
    }
    if (t < NCHUNK) g_bsumx[t] = ss[t] - orig;
    if (t == 511) g_off[NTOT] = ss[511];
}
// scan fixup + combo-id assignment in one pass
__global__ void k_scan3_cid() {
    int i = blockIdx.x * blockDim.x + threadIdx.x;
    if (i < NTOT) {
        int v = g_off[i] + g_bsumx[i >> 10];
        g_off[i] = v;
        g_cur[i] = v;
    }
    if (i < NA) {
        int d1 = g_deg[i], d2 = g_deg[NA + i];
        int cid;
        if (d1 < 64 && d2 < 64) cid = d1 * 64 + d2;
        else {
            int o = atomicAdd(&g_novf[0], 1);
            g_ovfA[o] = make_int2(d1, d2);
            cid = CGRID + o;
        }
        g_cidA[i] = cid;
    } else if (i < NA + NB) {
        int b = i - NA;
        int d = g_deg[2 * NA + b];
        int cid;
        if (d < CGRID) cid = d;
        else {
            int o = atomicAdd(&g_novf[1], 1);
            g_ovfB[o] = d;
            cid = CGRID + o;
        }
        g_cidB[b] = cid;
    }
}
// counting-sort fill; stores the SRC COMBO-ID (not the src id)
__global__ void k_fill_all(const int* __restrict__ s_aa, const int* __restrict__ d_aa, int Eaa,
                           const int* __restrict__ s_ba, const int* __restrict__ d_ba, int Eba,
                           const int* __restrict__ s_ab, const int* __restrict__ d_ab, int Eab) {
    int i = blockIdx.x * blockDim.x + threadIdx.x;
    int cid, base, dstv;
    if (i < Eaa) { cid = __ldg(&g_cidA[s_aa[i]]); dstv = d_aa[i]; base = 0; }
    else if (i < Eaa + Eba) { int j = i - Eaa; cid = __ldg(&g_cidB[s_ba[j]]); dstv = d_ba[j]; base = NA; }
    else if (i < Eaa + Eba + Eab) { int j = i - Eaa - Eba; cid = __ldg(&g_cidA[s_ab[j]]); dstv = d_ab[j]; base = 2 * NA; }
    else return;
    int pos = atomicAdd(&g_cur[base + dstv], 1);
    g_csr[pos] = cid;
}

// ======================= MMA helpers =========================================
__device__ __forceinline__ void mma_bf16(float c[4], const uint32_t a[4],
                                         uint32_t b0, uint32_t b1) {
    asm volatile("mma.sync.aligned.m16n8k16.row.col.f32.bf16.bf16.f32 "
                 "{%0,%1,%2,%3}, {%4,%5,%6,%7}, {%8,%9}, {%0,%1,%2,%3};"
                 : "+f"(c[0]), "+f"(c[1]), "+f"(c[2]), "+f"(c[3])
                 : "r"(a[0]), "r"(a[1]), "r"(a[2]), "r"(a[3]), "r"(b0), "r"(b1));
}
__device__ __forceinline__ void pack_hl(float x, float y, uint32_t& hi, uint32_t& lo) {
    __nv_bfloat162 H, L;
    H.x = __float2bfloat16(x); H.y = __float2bfloat16(y);
    L.x = __float2bfloat16(x - __bfloat162float(H.x));
    L.y = __float2bfloat16(y - __bfloat162float(H.y));
    hi = *reinterpret_cast<uint32_t*>(&H);
    lo = *reinterpret_cast<uint32_t*>(&L);
}
__device__ __forceinline__ void gemm_tile(float acc[8][4],
                                          const uint32_t* Ahi, const uint32_t* Alo,
                                          const __nv_bfloat16* whi, int g, int t) {
    const __nv_bfloat16* wlo = whi + 64 * AS;
#pragma unroll
    for (int nt = 0; nt < 8; nt++) {
        const __nv_bfloat16* bh = whi + (nt * 8 + g) * AS + 2 * t;
        const __nv_bfloat16* bl = wlo + (nt * 8 + g) * AS + 2 * t;
#pragma unroll
        for (int kc = 0; kc < 4; kc++) {
            uint32_t bh0 = *reinterpret_cast<const uint32_t*>(bh + kc * 16);
            uint32_t bh1 = *reinterpret_cast<const uint32_t*>(bh + kc * 16 + 8);
            uint32_t bl0 = *reinterpret_cast<const uint32_t*>(bl + kc * 16);
            uint32_t bl1 = *reinterpret_cast<const uint32_t*>(bl + kc * 16 + 8);
            mma_bf16(acc[nt], &Ahi[kc * 4], bh0, bh1);
            mma_bf16(acc[nt], &Ahi[kc * 4], bl0, bl1);
            mma_bf16(acc[nt], &Alo[kc * 4], bh0, bh1);
        }
    }
}
__device__ __forceinline__ void c2a(float acc[8][4], const float* __restrict__ bias,
                                    uint32_t A2hi[16], uint32_t A2lo[16], int t) {
#pragma unroll
    for (int kc = 0; kc < 4; kc++) {
        int nt0 = 2 * kc, nt1 = nt0 + 1;
        float b00 = __ldg(bias + nt0 * 8 + 2 * t), b01 = __ldg(bias + nt0 * 8 + 2 * t + 1);
        float b10 = __ldg(bias + nt1 * 8 + 2 * t), b11 = __ldg(bias + nt1 * 8 + 2 * t + 1);
        float x0 = fmaxf(acc[nt0][0] + b00, 0.f), x1 = fmaxf(acc[nt0][1] + b01, 0.f);
        float x2 = fmaxf(acc[nt0][2] + b00, 0.f), x3 = fmaxf(acc[nt0][3] + b01, 0.f);
        float y0 = fmaxf(acc[nt1][0] + b10, 0.f), y1 = fmaxf(acc[nt1][1] + b11, 0.f);
        float y2 = fmaxf(acc[nt1][2] + b10, 0.f), y3 = fmaxf(acc[nt1][3] + b11, 0.f);
        pack_hl(x0, x1, A2hi[kc * 4 + 0], A2lo[kc * 4 + 0]);
        pack_hl(x2, x3, A2hi[kc * 4 + 1], A2lo[kc * 4 + 1]);
        pack_hl(y0, y1, A2hi[kc * 4 + 2], A2lo[kc * 4 + 2]);
        pack_hl(y2, y3, A2hi[kc * 4 + 3], A2lo[kc * 4 + 3]);
    }
}
__device__ __forceinline__ void store_tile(float acc[8][4], const float* __restrict__ bias,
                                           float* __restrict__ out, int row0, int row1,
                                           int R, int t) {
#pragma unroll
    for (int nt = 0; nt < 8; nt++) {
        int col = nt * 8 + 2 * t;
        float bx = bias ? __ldg(bias + col) : 0.f;
        float by = bias ? __ldg(bias + col + 1) : 0.f;
        float2 v0 = make_float2(acc[nt][0] + bx, acc[nt][1] + by);
        float2 v1 = make_float2(acc[nt][2] + bx, acc[nt][3] + by);
        if (row0 < R) *reinterpret_cast<float2*>(out + (size_t)row0 * 64 + col) = v0;
        if (row1 < R) *reinterpret_cast<float2*>(out + (size_t)row1 * 64 + col) = v1;
    }
}
__device__ __forceinline__ void stage_w(__nv_bfloat16* sm, const float* const* wsrc,
                                        int nm, int tid) {
    for (int m = 0; m < nm; m++) {
        const float* w = wsrc[m];
        __nv_bfloat16* whi = sm + m * 2 * 64 * AS;
        __nv_bfloat16* wlo = whi + 64 * AS;
        for (int i = tid; i < 4096; i += 256) {
            int k = i >> 6, n = i & 63;
            float x = w[i];
            __nv_bfloat16 hi = __float2bfloat16(x);
            whi[n * AS + k] = hi;
            wlo[n * AS + k] = __float2bfloat16(x - __bfloat162float(hi));
        }
    }
}

// ======================= combo-table GEMM kernels =============================
#define SMEM_A_BYTES (5 * 2 * 64 * AS * 2)   // 92160
__global__ void __launch_bounds__(256) k_gemmA(
        const float* __restrict__ embA, const float* __restrict__ embB,
        const float* __restrict__ Waa0, const float* __restrict__ baa0,
        const float* __restrict__ Wba0, const float* __restrict__ bba0,
        const float* __restrict__ WnA0, const float* __restrict__ bnA0,
        const float* __restrict__ Waa1, const float* __restrict__ baa1,
        const float* __restrict__ Wab1, const float* __restrict__ bab1,
        const float* __restrict__ WnA1, const float* __restrict__ bnA1,
        const float* __restrict__ WnB1blk1) {
    int limit = CGRID + g_novf[0];
    if ((int)blockIdx.x * 128 >= limit) return;

    extern __shared__ __nv_bfloat16 sm[];
    __shared__ float sA[64], sB[64], v1[64], v2[64], sv[192];
    int tid = threadIdx.x;
    const float* wsrc[5] = { Waa1, Wab1, WnA1, WnA1 + 4096, WnB1blk1 };
    stage_w(sm, wsrc, 5, tid);
    if (tid < 64) { sA[tid] = embA[tid]; sB[tid] = embB[tid]; }
    __syncthreads();
    if (tid < 64) {
        int c = tid;
        float a0 = baa0[c], a2 = bba0[c];
        for (int k = 0; k < 64; k++) {
            a0 += sA[k] * Waa0[k * 64 + c];
            a2 += sB[k] * Wba0[k * 64 + c];
        }
        v1[c] = fmaxf(a0, 0.f); v2[c] = fmaxf(a2, 0.f);
    }
    __syncthreads();
    if (tid < 64) {
        int c = tid;
        float cA = bnA0[c], uaa = 0.f, uba = 0.f;
        for (int k = 0; k < 64; k++) {
            cA  += sA[k] * WnA0[k * 64 + c];
            uaa += v1[k] * WnA0[(64 + k) * 64 + c];
            uba += v2[k] * WnA0[(128 + k) * 64 + c];
        }
        sv[c] = cA; sv[64 + c] = uaa; sv[128 + c] = uba;
    }
    __syncthreads();

    int lane = tid & 31, wid = tid >> 5;
    int g = lane >> 2, t = lane & 3;
    int row0 = blockIdx.x * 128 + wid * 16 + g, row1 = row0 + 8;
    int r0 = min(row0, limit - 1), r1 = min(row1, limit - 1);
    float d10, d20, d11, d21;
    if (r0 < CGRID) { d10 = (float)(r0 >> 6); d20 = (float)(r0 & 63); }
    else { int2 dd = g_ovfA[r0 - CGRID]; d10 = (float)dd.x; d20 = (float)dd.y; }
    if (r1 < CGRID) { d11 = (float)(r1 >> 6); d21 = (float)(r1 & 63); }
    else { int2 dd = g_ovfA[r1 - CGRID]; d11 = (float)dd.x; d21 = (float)dd.y; }

    uint32_t Ahi[16], Alo[16];
#pragma unroll
    for (int kc = 0; kc < 4; kc++) {
        int c0 = kc * 16 + 2 * t;
#pragma unroll
        for (int half = 0; half < 2; half++) {
            int c = c0 + half * 8;
            float p0 = sv[c],     u0 = sv[64 + c],     w0 = sv[128 + c];
            float p1 = sv[c + 1], u1 = sv[64 + c + 1], w1 = sv[128 + c + 1];
            float h00 = fmaxf(p0 + d10 * u0 + d20 * w0, 0.f);
            float h01 = fmaxf(p1 + d10 * u1 + d20 * w1, 0.f);
            float h10 = fmaxf(p0 + d11 * u0 + d21 * w0, 0.f);
            float h11 = fmaxf(p1 + d11 * u1 + d21 * w1, 0.f);
            pack_hl(h00, h01, Ahi[kc * 4 + half * 2 + 0], Alo[kc * 4 + half * 2 + 0]);
            pack_hl(h10, h11, Ahi[kc * 4 + half * 2 + 1], Alo[kc * 4 + half * 2 + 1]);
        }
    }

    float acc[8][4], acc2[8][4];
    uint32_t A2hi[16], A2lo[16];

#pragma unroll
    for (int nt = 0; nt < 8; nt++) { acc[nt][0]=0.f; acc[nt][1]=0.f; acc[nt][2]=0.f; acc[nt][3]=0.f; }
    gemm_tile(acc, Ahi, Alo, sm + 2 * 2 * 64 * AS, g, t);
    store_tile(acc, bnA1, g_TzA, row0, row1, limit, t);

#pragma unroll
    for (int nt = 0; nt < 8; nt++) { acc[nt][0]=0.f; acc[nt][1]=0.f; acc[nt][2]=0.f; acc[nt][3]=0.f; }
    gemm_tile(acc, Ahi, Alo, sm, g, t);
    c2a(acc, baa1, A2hi, A2lo, t);
#pragma unroll
    for (int nt = 0; nt < 8; nt++) { acc2[nt][0]=0.f; acc2[nt][1]=0.f; acc2[nt][2]=0.f; acc2[nt][3]=0.f; }
    gemm_tile(acc2, A2hi, A2lo, sm + 3 * 2 * 64 * AS, g, t);
    store_tile(acc2, nullptr, g_Taa, row0, row1, limit, t);

#pragma unroll
    for (int nt = 0; nt < 8; nt++) { acc[nt][0]=0.f; acc[nt][1]=0.f; acc[nt][2]=0.f; acc[nt][3]=0.f; }
    gemm_tile(acc, Ahi, Alo, sm + 1 * 2 * 64 * AS, g, t);
    c2a(acc, bab1, A2hi, A2lo, t);
#pragma unroll
    for (int nt = 0; nt < 8; nt++) { acc2[nt][0]=0.f; acc2[nt][1]=0.f; acc2[nt][2]=0.f; acc2[nt][3]=0.f; }
    gemm_tile(acc2, A2hi, A2lo, sm + 4 * 2 * 64 * AS, g, t);
    store_tile(acc2, nullptr, g_Tab, row0, row1, limit, t);
}

#define SMEM_B_BYTES (3 * 2 * 64 * AS * 2)   // 55296
__global__ void __launch_bounds__(256) k_gemmB(
        const float* __restrict__ embA, const float* __restrict__ embB,
        const float* __restrict__ Wab0, const float* __restrict__ bab0,
        const float* __restrict__ WnB0, const float* __restrict__ bnB0,
        const float* __restrict__ Wba1, const float* __restrict__ bba1,
        const float* __restrict__ WnB1, const float* __restrict__ bnB1,
        const float* __restrict__ WnA1blk2) {
    int limit = CGRID + g_novf[1];
    if ((int)blockIdx.x * 128 >= limit) return;

    extern __shared__ __nv_bfloat16 sm[];
    __shared__ float sA[64], sB[64], v1[64], sv[128];
    int tid = threadIdx.x;
    const float* wsrc[3] = { Wba1, WnB1, WnA1blk2 };
    stage_w(sm, wsrc, 3, tid);
    if (tid < 64) { sA[tid] = embA[tid]; sB[tid] = embB[tid]; }
    __syncthreads();
    if (tid < 64) {
        int c = tid;
        float a1 = bab0[c];
        for (int k = 0; k < 64; k++) a1 += sA[k] * Wab0[k * 64 + c];
        v1[c] = fmaxf(a1, 0.f);
    }
    __syncthreads();
    if (tid < 64) {
        int c = tid;
        float cB = bnB0[c], uab = 0.f;
        for (int k = 0; k < 64; k++) {
            cB  += sB[k] * WnB0[k * 64 + c];
            uab += v1[k] * WnB0[(64 + k) * 64 + c];
        }
        sv[c] = cB; sv[64 + c] = uab;
    }
    __syncthreads();

    int lane = tid & 31, wid = tid >> 5;
    int g = lane >> 2, t = lane & 3;
    int row0 = blockIdx.x * 128 + wid * 16 + g, row1 = row0 + 8;
    int r0 = min(row0, limit - 1), r1 = min(row1, limit - 1);
    float d0 = (r0 < CGRID) ? (float)r0 : (float)g_ovfB[r0 - CGRID];
    float d1 = (r1 < CGRID) ? (float)r1 : (float)g_ovfB[r1 - CGRID];

    uint32_t Ahi[16], Alo[16];
#pragma unroll
    for (int kc = 0; kc < 4; kc++) {
        int c0 = kc * 16 + 2 * t;
#pragma unroll
        for (int half = 0; half < 2; half++) {
            int c = c0 + half * 8;
            float p0 = sv[c],     u0 = sv[64 + c];
            float p1 = sv[c + 1], u1 = sv[64 + c + 1];
            float h00 = fmaxf(p0 + d0 * u0, 0.f);
            float h01 = fmaxf(p1 + d0 * u1, 0.f);
            float h10 = fmaxf(p0 + d1 * u0, 0.f);
            float h11 = fmaxf(p1 + d1 * u1, 0.f);
            pack_hl(h00, h01, Ahi[kc * 4 + half * 2 + 0], Alo[kc * 4 + half * 2 + 0]);
            pack_hl(h10, h11, Ahi[kc * 4 + half * 2 + 1], Alo[kc * 4 + half * 2 + 1]);
        }
    }

    float acc[8][4], acc2[8][4];
    uint32_t A2hi[16], A2lo[16];

#pragma unroll
    for (int nt = 0; nt < 8; nt++) { acc[nt][0]=0.f; acc[nt][1]=0.f; acc[nt][2]=0.f; acc[nt][3]=0.f; }
    gemm_tile(acc, Ahi, Alo, sm + 1 * 2 * 64 * AS, g, t);
    store_tile(acc, bnB1, g_TzB, row0, row1, limit, t);

#pragma unroll
    for (int nt = 0; nt < 8; nt++) { acc[nt][0]=0.f; acc[nt][1]=0.f; acc[nt][2]=0.f; acc[nt][3]=0.f; }
    gemm_tile(acc, Ahi, Alo, sm, g, t);
    c2a(acc, bba1, A2hi, A2lo, t);
#pragma unroll
    for (int nt = 0; nt < 8; nt++) { acc2[nt][0]=0.f; acc2[nt][1]=0.f; acc2[nt][2]=0.f; acc2[nt][3]=0.f; }
    gemm_tile(acc2, A2hi, A2lo, sm + 2 * 2 * 64 * AS, g, t);
    store_tile(acc2, nullptr, g_Tba, row0, row1, limit, t);
}

// ======================= fused gather (cid-CSR, cooperative index load) =======
// segment sum: lane l loads csr[b+l] (coalesced), shfl broadcasts; table rows L1-hot
__device__ __forceinline__ void seg_sum(float2& s, int b, int e,
                                        const float* __restrict__ T, int lane) {
    int cnt = e - b;
    for (int base = 0; base < cnt; base += 32) {
        int rem = cnt - base;
        int m = rem < 32 ? rem : 32;
        int idx = (lane < m) ? __ldg(&g_csr[b + base + lane]) : 0;
        int k = 0;
        for (; k + 1 < m; k += 2) {
            int c0 = __shfl_sync(0xffffffffu, idx, k);
            int c1 = __shfl_sync(0xffffffffu, idx, k + 1);
            float2 p = *reinterpret_cast<const float2*>(T + (size_t)c0 * 64 + lane * 2);
            float2 q = *reinterpret_cast<const float2*>(T + (size_t)c1 * 64 + lane * 2);
            s.x += p.x + q.x; s.y += p.y + q.y;
        }
        if (k < m) {
            int c0 = __shfl_sync(0xffffffffu, idx, k);
            float2 p = *reinterpret_cast<const float2*>(T + (size_t)c0 * 64 + lane * 2);
            s.x += p.x; s.y += p.y;
        }
    }
}

__global__ void __launch_bounds__(256) k_gather(float* __restrict__ out) {
    int row = blockIdx.x * 8 + (threadIdx.x >> 5);
    if (row >= NA + NB) return;
    int lane = threadIdx.x & 31;
    float2 s;
    if (row < NA) {
        int cself = __ldg(&g_cidA[row]);
        s = *reinterpret_cast<const float2*>(g_TzA + (size_t)cself * 64 + lane * 2);
        seg_sum(s, g_off[row],      g_off[row + 1],      g_Taa, lane);
        seg_sum(s, g_off[NA + row], g_off[NA + row + 1], g_Tba, lane);
    } else {
        int rb = row - NA;
        int cself = __ldg(&g_cidB[rb]);
        s = *reinterpret_cast<const float2*>(g_TzB + (size_t)cself * 64 + lane * 2);
        seg_sum(s, g_off[2 * NA + rb], g_off[2 * NA + rb + 1], g_Tab, lane);
    }
    s.x = fmaxf(s.x, 0.f); s.y = fmaxf(s.y, 0.f);
    *reinterpret_cast<float2*>(out + (size_t)row * 64 + lane * 2) = s;
}

// ==============================================================================
extern "C" void kernel_launch(void* const* d_in, const int* in_sizes, int n_in,
                              void* d_out, int out_size) {
    const int*   src_aa = (const int*)d_in[0];
    const int*   dst_aa = (const int*)d_in[1];
    const int*   src_ab = (const int*)d_in[2];
    const int*   dst_ab = (const int*)d_in[3];
    const int*   src_ba = (const int*)d_in[4];
    const int*   dst_ba = (const int*)d_in[5];
    const float* embA   = (const float*)d_in[6];
    const float* embB   = (const float*)d_in[7];
    const float* Waa    = (const float*)d_in[8];
    const float* baa    = (const float*)d_in[9];
    const float* Wab    = (const float*)d_in[10];
    const float* bab    = (const float*)d_in[11];
    const float* Wba    = (const float*)d_in[12];
    const float* bba    = (const float*)d_in[13];
    const float* WnA    = (const float*)d_in[14];
    const float* bnA    = (const float*)d_in[15];
    const float* WnB    = (const float*)d_in[16];
    const float* bnB    = (const float*)d_in[17];
    const int Eaa = in_sizes[0];
    const int Eab = in_sizes[2];
    const int Eba = in_sizes[4];
    const int Etot = Eaa + Eba + Eab;
    float* out = (float*)d_out;

    cudaFuncSetAttribute(k_gemmA, cudaFuncAttributeMaxDynamicSharedMemorySize, SMEM_A_BYTES);
    cudaFuncSetAttribute(k_gemmB, cudaFuncAttributeMaxDynamicSharedMemorySize, SMEM_B_BYTES);

    const float* Waa1 = Waa + 4096;
    const float* Wab1 = Wab + 4096;
    const float* Wba1 = Wba + 4096;
    const float* baa1 = baa + 64;
    const float* bab1 = bab + 64;
    const float* bba1 = bba + 64;
    const float* WnA1 = WnA + 192 * 64;
    const float* WnB1 = WnB + 128 * 64;
    const float* bnA1 = bnA + 64;
    const float* bnB1 = bnB + 64;

    void *p_deg, *p_novf;
    cudaGetSymbolAddress(&p_deg, g_deg);
    cudaGetSymbolAddress(&p_novf, g_novf);

    cudaMemsetAsync(p_deg, 0, sizeof(int) * NTOT);
    cudaMemsetAsync(p_novf, 0, sizeof(int) * 2);

    k_deg_all<<<(Etot + 255) / 256, 256>>>(dst_aa, Eaa, dst_ba, Eba, dst_ab, Eab);
    k_scan1<<<NCHUNK, 256>>>();
    k_scan2<<<1, 512>>>();
    k_scan3_cid<<<(NTOT + 255) / 256, 256>>>();

    k_gemmA<<<(CGRID + NA + 127) / 128, 256, SMEM_A_BYTES>>>(
        embA, embB, Waa, baa, Wba, bba, WnA, bnA,
        Waa1, baa1, Wab1, bab1, WnA1, bnA1, WnB1 + 4096);
    k_gemmB<<<(CGRID + NB + 127) / 128, 256, SMEM_B_BYTES>>>(
        embA, embB, Wab, bab, WnB, bnB,
        Wba1, bba1, WnB1, bnB1, WnA1 + 2 * 4096);

    k_fill_all<<<(Etot + 255) / 256, 256>>>(src_aa, dst_aa, Eaa,
                                            src_ba, dst_ba, Eba,
                                            src_ab, dst_ab, Eab);

    k_gather<<<(NA + NB + 7) / 8, 256>>>(out);
}

// round 8
// speedup vs baseline: 8.0803x; 1.1683x over previous
#include <cuda_runtime.h>
#include <cuda_bf16.h>
#include <cstdint>

#define NA 100000
#define NB 100000
#define D 64
#define NTOT (NA + NA + NB)                 // deg/off layout: [aa->A | ba->A | ab->B]
#define ECAP 2000000
#define AS 72                               // smem row stride (bf16), conflict-free
#define CGRID 4096                          // 64x64 degree-pair grid (A); 1-D for B
#define TROWSA (CGRID + NA)
#define TROWSB (CGRID + NB)
#define SCAN_NBLK ((NTOT + 1023) / 1024)    // 293

// ======================= scratch (zero-initialized at module load) ===========
__device__ int      g_deg[NTOT];            // zeroed at end of every run
__device__ unsigned g_state[SCAN_NBLK];     // scan lookback state; zeroed at end
__device__ int      g_novf[2];              // overflow counters; zeroed at end
__device__ int      g_off[NTOT + 1];
__device__ int      g_cur[NTOT];
__device__ int      g_csr[ECAP];            // combo-id of src, grouped by dst
__device__ int      g_cidA[NA];
__device__ int      g_cidB[NB];
__device__ int2     g_ovfA[NA];
__device__ int      g_ovfB[NB];
__device__ float    g_TzA[TROWSA * D];
__device__ float    g_Taa[TROWSA * D];
__device__ float    g_Tab[TROWSA * D];
__device__ float    g_TzB[TROWSB * D];
__device__ float    g_Tba[TROWSB * D];

// ======================= sparse machinery ====================================
__global__ void k_deg_all(const int* __restrict__ d_aa, int Eaa,
                          const int* __restrict__ d_ba, int Eba,
                          const int* __restrict__ d_ab, int Eab) {
    int i = blockIdx.x * blockDim.x + threadIdx.x;
    if (i < Eaa) {
        atomicAdd(&g_deg[d_aa[i]], 1);
    } else if (i < Eaa + Eba) {
        atomicAdd(&g_deg[NA + d_ba[i - Eaa]], 1);
    } else if (i < Eaa + Eba + Eab) {
        atomicAdd(&g_deg[2 * NA + d_ab[i - Eaa - Eba]], 1);
    }
}

// single-pass decoupled-lookback exclusive scan + combo-id assignment.
// All SCAN_NBLK blocks are simultaneously resident (2 blocks/SM), so polling
// predecessors cannot deadlock.
__global__ void __launch_bounds__(1024) k_scan_cid() {
    __shared__ int wsum[32];
    __shared__ int s_total, s_prefix;
    int b = blockIdx.x, t = threadIdx.x;
    int i = b * 1024 + t;
    int v = (i < NTOT) ? g_deg[i] : 0;
    int x = v;
#pragma unroll
    for (int o = 1; o < 32; o <<= 1) {
        int y = __shfl_up_sync(0xffffffffu, x, o);
        if ((t & 31) >= o) x += y;
    }
    if ((t & 31) == 31) wsum[t >> 5] = x;
    __syncthreads();
    if (t < 32) {
        int w = wsum[t];
        int xx = w;
#pragma unroll
        for (int o = 1; o < 32; o <<= 1) {
            int y = __shfl_up_sync(0xffffffffu, xx, o);
            if (t >= o) xx += y;
        }
        wsum[t] = xx - w;
        if (t == 31) {
            s_total = xx;
            unsigned st = ((b == 0 ? 2u : 1u) << 30) | (unsigned)xx;
            atomicExch(&g_state[b], st);   // flag|sum in one word: atomic publish
        }
    }
    __syncthreads();
    int excl = x - v + wsum[t >> 5];
    if (t == 0) {
        int pref = 0;
        if (b > 0) {
            int j = b - 1;
            while (true) {
                unsigned st = atomicAdd(&g_state[j], 0u);
                unsigned f = st >> 30;
                if (f == 0) continue;
                pref += (int)(st & 0x3FFFFFFFu);
                if (f >= 2) break;
                j--;
            }
            atomicExch(&g_state[b], (2u << 30) | (unsigned)(pref + s_total));
        }
        s_prefix = pref;
    }
    __syncthreads();
    int off = s_prefix + excl;
    if (i < NTOT) { g_off[i] = off; g_cur[i] = off; }
    if (i == NTOT - 1) g_off[NTOT] = off + v;

    // combo-id assignment (reuses v = g_deg[i]; partner degree at g_deg[NA+i])
    if (i < NA) {
        int d1 = v, d2 = g_deg[NA + i];
        int cid;
        if (d1 < 64 && d2 < 64) cid = d1 * 64 + d2;
        else { int o = atomicAdd(&g_novf[0], 1); g_ovfA[o] = make_int2(d1, d2); cid = CGRID + o; }
        g_cidA[i] = cid;
    } else if (i < NA + NB) {
        int d = g_deg[NA + i];              // == g_deg[2*NA + (i-NA)]
        int cid;
        if (d < CGRID) cid = d;
        else { int o = atomicAdd(&g_novf[1], 1); g_ovfB[o] = d; cid = CGRID + o; }
        g_cidB[i - NA] = cid;
    }
}

// counting-sort fill; stores the SRC COMBO-ID
__global__ void k_fill_all(const int* __restrict__ s_aa, const int* __restrict__ d_aa, int Eaa,
                           const int* __restrict__ s_ba, const int* __restrict__ d_ba, int Eba,
                           const int* __restrict__ s_ab, const int* __restrict__ d_ab, int Eab) {
    int i = blockIdx.x * blockDim.x + threadIdx.x;
    int cid, base, dstv;
    if (i < Eaa) { cid = __ldg(&g_cidA[s_aa[i]]); dstv = d_aa[i]; base = 0; }
    else if (i < Eaa + Eba) { int j = i - Eaa; cid = __ldg(&g_cidB[s_ba[j]]); dstv = d_ba[j]; base = NA; }
    else if (i < Eaa + Eba + Eab) { int j = i - Eaa - Eba; cid = __ldg(&g_cidA[s_ab[j]]); dstv = d_ab[j]; base = 2 * NA; }
    else return;
    int pos = atomicAdd(&g_cur[base + dstv], 1);
    g_csr[pos] = cid;
}

// zero scratch at END of run (module load provides the initial zeros)
__global__ void k_zero_end() {
    int i = blockIdx.x * blockDim.x + threadIdx.x;
    if (i < NTOT / 4) reinterpret_cast<int4*>(g_deg)[i] = make_int4(0, 0, 0, 0);
    if (i < SCAN_NBLK) g_state[i] = 0;
    if (i == 0) { g_novf[0] = 0; g_novf[1] = 0; }
}

// ======================= MMA helpers =========================================
__device__ __forceinline__ void mma_bf16(float c[4], const uint32_t a[4],
                                         uint32_t b0, uint32_t b1) {
    asm volatile("mma.sync.aligned.m16n8k16.row.col.f32.bf16.bf16.f32 "
                 "{%0,%1,%2,%3}, {%4,%5,%6,%7}, {%8,%9}, {%0,%1,%2,%3};"
                 : "+f"(c[0]), "+f"(c[1]), "+f"(c[2]), "+f"(c[3])
                 : "r"(a[0]), "r"(a[1]), "r"(a[2]), "r"(a[3]), "r"(b0), "r"(b1));
}
__device__ __forceinline__ void pack_hl(float x, float y, uint32_t& hi, uint32_t& lo) {
    __nv_bfloat162 H, L;
    H.x = __float2bfloat16(x); H.y = __float2bfloat16(y);
    L.x = __float2bfloat16(x - __bfloat162float(H.x));
    L.y = __float2bfloat16(y - __bfloat162float(H.y));
    hi = *reinterpret_cast<uint32_t*>(&H);
    lo = *reinterpret_cast<uint32_t*>(&L);
}
__device__ __forceinline__ void gemm_tile(float acc[8][4],
                                          const uint32_t* Ahi, const uint32_t* Alo,
                                          const __nv_bfloat16* whi, int g, int t) {
    const __nv_bfloat16* wlo = whi + 64 * AS;
#pragma unroll
    for (int nt = 0; nt < 8; nt++) {
        const __nv_bfloat16* bh = whi + (nt * 8 + g) * AS + 2 * t;
        const __nv_bfloat16* bl = wlo + (nt * 8 + g) * AS + 2 * t;
#pragma unroll
        for (int kc = 0; kc < 4; kc++) {
            uint32_t bh0 = *reinterpret_cast<const uint32_t*>(bh + kc * 16);
            uint32_t bh1 = *reinterpret_cast<const uint32_t*>(bh + kc * 16 + 8);
            uint32_t bl0 = *reinterpret_cast<const uint32_t*>(bl + kc * 16);
            uint32_t bl1 = *reinterpret_cast<const uint32_t*>(bl + kc * 16 + 8);
            mma_bf16(acc[nt], &Ahi[kc * 4], bh0, bh1);
            mma_bf16(acc[nt], &Ahi[kc * 4], bl0, bl1);
            mma_bf16(acc[nt], &Alo[kc * 4], bh0, bh1);
        }
    }
}
__device__ __forceinline__ void c2a(float acc[8][4], const float* __restrict__ bias,
                                    uint32_t A2hi[16], uint32_t A2lo[16], int t) {
#pragma unroll
    for (int kc = 0; kc < 4; kc++) {
        int nt0 = 2 * kc, nt1 = nt0 + 1;
        float b00 = __ldg(bias + nt0 * 8 + 2 * t), b01 = __ldg(bias + nt0 * 8 + 2 * t + 1);
        float b10 = __ldg(bias + nt1 * 8 + 2 * t), b11 = __ldg(bias + nt1 * 8 + 2 * t + 1);
        float x0 = fmaxf(acc[nt0][0] + b00, 0.f), x1 = fmaxf(acc[nt0][1] + b01, 0.f);
        float x2 = fmaxf(acc[nt0][2] + b00, 0.f), x3 = fmaxf(acc[nt0][3] + b01, 0.f);
        float y0 = fmaxf(acc[nt1][0] + b10, 0.f), y1 = fmaxf(acc[nt1][1] + b11, 0.f);
        float y2 = fmaxf(acc[nt1][2] + b10, 0.f), y3 = fmaxf(acc[nt1][3] + b11, 0.f);
        pack_hl(x0, x1, A2hi[kc * 4 + 0], A2lo[kc * 4 + 0]);
        pack_hl(x2, x3, A2hi[kc * 4 + 1], A2lo[kc * 4 + 1]);
        pack_hl(y0, y1, A2hi[kc * 4 + 2], A2lo[kc * 4 + 2]);
        pack_hl(y2, y3, A2hi[kc * 4 + 3], A2lo[kc * 4 + 3]);
    }
}
__device__ __forceinline__ void store_tile(float acc[8][4], const float* __restrict__ bias,
                                           float* __restrict__ out, int row0, int row1,
                                           int R, int t) {
#pragma unroll
    for (int nt = 0; nt < 8; nt++) {
        int col = nt * 8 + 2 * t;
        float bx = bias ? __ldg(bias + col) : 0.f;
        float by = bias ? __ldg(bias + col + 1) : 0.f;
        float2 v0 = make_float2(acc[nt][0] + bx, acc[nt][1] + by);
        float2 v1 = make_float2(acc[nt][2] + bx, acc[nt][3] + by);
        if (row0 < R) *reinterpret_cast<float2*>(out + (size_t)row0 * 64 + col) = v0;
        if (row1 < R) *reinterpret_cast<float2*>(out + (size_t)row1 * 64 + col) = v1;
    }
}
__device__ __forceinline__ void stage_w(__nv_bfloat16* sm, const float* const* wsrc,
                                        int nm, int tid) {
    for (int m = 0; m < nm; m++) {
        const float* w = wsrc[m];
        __nv_bfloat16* whi = sm + m * 2 * 64 * AS;
        __nv_bfloat16* wlo = whi + 64 * AS;
        for (int i = tid; i < 4096; i += 256) {
            int k = i >> 6, n = i & 63;
            float x = w[i];
            __nv_bfloat16 hi = __float2bfloat16(x);
            whi[n * AS + k] = hi;
            wlo[n * AS + k] = __float2bfloat16(x - __bfloat162float(hi));
        }
    }
}

// ======================= combo-table GEMM kernels =============================
// is_ovf=0: rows [0, CGRID) (weights-only dependency; runs on side stream early)
// is_ovf=1: rows [CGRID, CGRID+novf) (depends on scan; usually empty)
#define SMEM_A_BYTES (5 * 2 * 64 * AS * 2)   // 92160
__global__ void __launch_bounds__(256) k_gemmA(
        const float* __restrict__ embA, const float* __restrict__ embB,
        const float* __restrict__ Waa0, const float* __restrict__ baa0,
        const float* __restrict__ Wba0, const float* __restrict__ bba0,
        const float* __restrict__ WnA0, const float* __restrict__ bnA0,
        const float* __restrict__ Waa1, const float* __restrict__ baa1,
        const float* __restrict__ Wab1, const float* __restrict__ bab1,
        const float* __restrict__ WnA1, const float* __restrict__ bnA1,
        const float* __restrict__ WnB1blk1, int is_ovf) {
    int row_off = is_ovf ? CGRID : 0;
    int nrows   = is_ovf ? g_novf[0] : CGRID;
    if ((int)blockIdx.x * 128 >= nrows) return;
    int limit = row_off + nrows;

    extern __shared__ __nv_bfloat16 sm[];
    __shared__ float sA[64], sB[64], v1[64], v2[64], sv[192];
    int tid = threadIdx.x;
    const float* wsrc[5] = { Waa1, Wab1, WnA1, WnA1 + 4096, WnB1blk1 };
    stage_w(sm, wsrc, 5, tid);
    if (tid < 64) { sA[tid] = embA[tid]; sB[tid] = embB[tid]; }
    __syncthreads();
    if (tid < 64) {
        int c = tid;
        float a0 = baa0[c], a2 = bba0[c];
        for (int k = 0; k < 64; k++) {
            a0 += sA[k] * Waa0[k * 64 + c];
            a2 += sB[k] * Wba0[k * 64 + c];
        }
        v1[c] = fmaxf(a0, 0.f); v2[c] = fmaxf(a2, 0.f);
    }
    __syncthreads();
    if (tid < 64) {
        int c = tid;
        float cA = bnA0[c], uaa = 0.f, uba = 0.f;
        for (int k = 0; k < 64; k++) {
            cA  += sA[k] * WnA0[k * 64 + c];
            uaa += v1[k] * WnA0[(64 + k) * 64 + c];
            uba += v2[k] * WnA0[(128 + k) * 64 + c];
        }
        sv[c] = cA; sv[64 + c] = uaa; sv[128 + c] = uba;
    }
    __syncthreads();

    int lane = tid & 31, wid = tid >> 5;
    int g = lane >> 2, t = lane & 3;
    int row0 = row_off + blockIdx.x * 128 + wid * 16 + g, row1 = row0 + 8;
    int r0 = min(row0, limit - 1), r1 = min(row1, limit - 1);
    float d10, d20, d11, d21;
    if (r0 < CGRID) { d10 = (float)(r0 >> 6); d20 = (float)(r0 & 63); }
    else { int2 dd = g_ovfA[r0 - CGRID]; d10 = (float)dd.x; d20 = (float)dd.y; }
    if (r1 < CGRID) { d11 = (float)(r1 >> 6); d21 = (float)(r1 & 63); }
    else { int2 dd = g_ovfA[r1 - CGRID]; d11 = (float)dd.x; d21 = (float)dd.y; }

    uint32_t Ahi[16], Alo[16];
#pragma unroll
    for (int kc = 0; kc < 4; kc++) {
        int c0 = kc * 16 + 2 * t;
#pragma unroll
        for (int half = 0; half < 2; half++) {
            int c = c0 + half * 8;
            float p0 = sv[c],     u0 = sv[64 + c],     w0 = sv[128 + c];
            float p1 = sv[c + 1], u1 = sv[64 + c + 1], w1 = sv[128 + c + 1];
            float h00 = fmaxf(p0 + d10 * u0 + d20 * w0, 0.f);
            float h01 = fmaxf(p1 + d10 * u1 + d20 * w1, 0.f);
            float h10 = fmaxf(p0 + d11 * u0 + d21 * w0, 0.f);
            float h11 = fmaxf(p1 + d11 * u1 + d21 * w1, 0.f);
            pack_hl(h00, h01, Ahi[kc * 4 + half * 2 + 0], Alo[kc * 4 + half * 2 + 0]);
            pack_hl(h10, h11, Ahi[kc * 4 + half * 2 + 1], Alo[kc * 4 + half * 2 + 1]);
        }
    }

    float acc[8][4], acc2[8][4];
    uint32_t A2hi[16], A2lo[16];

#pragma unroll
    for (int nt = 0; nt < 8; nt++) { acc[nt][0]=0.f; acc[nt][1]=0.f; acc[nt][2]=0.f; acc[nt][3]=0.f; }
    gemm_tile(acc, Ahi, Alo, sm + 2 * 2 * 64 * AS, g, t);
    store_tile(acc, bnA1, g_TzA, row0, row1, limit, t);

#pragma unroll
    for (int nt = 0; nt < 8; nt++) { acc[nt][0]=0.f; acc[nt][1]=0.f; acc[nt][2]=0.f; acc[nt][3]=0.f; }
    gemm_tile(acc, Ahi, Alo, sm, g, t);
    c2a(acc, baa1, A2hi, A2lo, t);
#pragma unroll
    for (int nt = 0; nt < 8; nt++) { acc2[nt][0]=0.f; acc2[nt][1]=0.f; acc2[nt][2]=0.f; acc2[nt][3]=0.f; }
    gemm_tile(acc2, A2hi, A2lo, sm + 3 * 2 * 64 * AS, g, t);
    store_tile(acc2, nullptr, g_Taa, row0, row1, limit, t);

#pragma unroll
    for (int nt = 0; nt < 8; nt++) { acc[nt][0]=0.f; acc[nt][1]=0.f; acc[nt][2]=0.f; acc[nt][3]=0.f; }
    gemm_tile(acc, Ahi, Alo, sm + 1 * 2 * 64 * AS, g, t);
    c2a(acc, bab1, A2hi, A2lo, t);
#pragma unroll
    for (int nt = 0; nt < 8; nt++) { acc2[nt][0]=0.f; acc2[nt][1]=0.f; acc2[nt][2]=0.f; acc2[nt][3]=0.f; }
    gemm_tile(acc2, A2hi, A2lo, sm + 4 * 2 * 64 * AS, g, t);
    store_tile(acc2, nullptr, g_Tab, row0, row1, limit, t);
}

#define SMEM_B_BYTES (3 * 2 * 64 * AS * 2)   // 55296
__global__ void __launch_bounds__(256) k_gemmB(
        const float* __restrict__ embA, const float* __restrict__ embB,
        const float* __restrict__ Wab0, const float* __restrict__ bab0,
        const float* __restrict__ WnB0, const float* __restrict__ bnB0,
        const float* __restrict__ Wba1, const float* __restrict__ bba1,
        const float* __restrict__ WnB1, const float* __restrict__ bnB1,
        const float* __restrict__ WnA1blk2, int is_ovf) {
    int row_off = is_ovf ? CGRID : 0;
    int nrows   = is_ovf ? g_novf[1] : CGRID;
    if ((int)blockIdx.x * 128 >= nrows) return;
    int limit = row_off + nrows;

    extern __shared__ __nv_bfloat16 sm[];
    __shared__ float sA[64], sB[64], v1[64], sv[128];
    int tid = threadIdx.x;
    const float* wsrc[3] = { Wba1, WnB1, WnA1blk2 };
    stage_w(sm, wsrc, 3, tid);
    if (tid < 64) { sA[tid] = embA[tid]; sB[tid] = embB[tid]; }
    __syncthreads();
    if (tid < 64) {
        int c = tid;
        float a1 = bab0[c];
        for (int k = 0; k < 64; k++) a1 += sA[k] * Wab0[k * 64 + c];
        v1[c] = fmaxf(a1, 0.f);
    }
    __syncthreads();
    if (tid < 64) {
        int c = tid;
        float cB = bnB0[c], uab = 0.f;
        for (int k = 0; k < 64; k++) {
            cB  += sB[k] * WnB0[k * 64 + c];
            uab += v1[k] * WnB0[(64 + k) * 64 + c];
        }
        sv[c] = cB; sv[64 + c] = uab;
    }
    __syncthreads();

    int lane = tid & 31, wid = tid >> 5;
    int g = lane >> 2, t = lane & 3;
    int row0 = row_off + blockIdx.x * 128 + wid * 16 + g, row1 = row0 + 8;
    int r0 = min(row0, limit - 1), r1 = min(row1, limit - 1);
    float d0 = (r0 < CGRID) ? (float)r0 : (float)g_ovfB[r0 - CGRID];
    float d1 = (r1 < CGRID) ? (float)r1 : (float)g_ovfB[r1 - CGRID];

    uint32_t Ahi[16], Alo[16];
#pragma unroll
    for (int kc = 0; kc < 4; kc++) {
        int c0 = kc * 16 + 2 * t;
#pragma unroll
        for (int half = 0; half < 2; half++) {
            int c = c0 + half * 8;
            float p0 = sv[c],     u0 = sv[64 + c];
            float p1 = sv[c + 1], u1 = sv[64 + c + 1];
            float h00 = fmaxf(p0 + d0 * u0, 0.f);
            float h01 = fmaxf(p1 + d0 * u1, 0.f);
            float h10 = fmaxf(p0 + d1 * u0, 0.f);
            float h11 = fmaxf(p1 + d1 * u1, 0.f);
            pack_hl(h00, h01, Ahi[kc * 4 + half * 2 + 0], Alo[kc * 4 + half * 2 + 0]);
            pack_hl(h10, h11, Ahi[kc * 4 + half * 2 + 1], Alo[kc * 4 + half * 2 + 1]);
        }
    }

    float acc[8][4], acc2[8][4];
    uint32_t A2hi[16], A2lo[16];

#pragma unroll
    for (int nt = 0; nt < 8; nt++) { acc[nt][0]=0.f; acc[nt][1]=0.f; acc[nt][2]=0.f; acc[nt][3]=0.f; }
    gemm_tile(acc, Ahi, Alo, sm + 1 * 2 * 64 * AS, g, t);
    store_tile(acc, bnB1, g_TzB, row0, row1, limit, t);

#pragma unroll
    for (int nt = 0; nt < 8; nt++) { acc[nt][0]=0.f; acc[nt][1]=0.f; acc[nt][2]=0.f; acc[nt][3]=0.f; }
    gemm_tile(acc, Ahi, Alo, sm, g, t);
    c2a(acc, bba1, A2hi, A2lo, t);
#pragma unroll
    for (int nt = 0; nt < 8; nt++) { acc2[nt][0]=0.f; acc2[nt][1]=0.f; acc2[nt][2]=0.f; acc2[nt][3]=0.f; }
    gemm_tile(acc2, A2hi, A2lo, sm + 2 * 2 * 64 * AS, g, t);
    store_tile(acc2, nullptr, g_Tba, row0, row1, limit, t);
}

// ======================= fused gather =========================================
__device__ __forceinline__ void seg_sum(float2& s, int b, int e,
                                        const float* __restrict__ T, int lane) {
    int cnt = e - b;
    for (int base = 0; base < cnt; base += 32) {
        int rem = cnt - base;
        int m = rem < 32 ? rem : 32;
        int idx = (lane < m) ? __ldg(&g_csr[b + base + lane]) : 0;
        int k = 0;
        for (; k + 1 < m; k += 2) {
            int c0 = __shfl_sync(0xffffffffu, idx, k);
            int c1 = __shfl_sync(0xffffffffu, idx, k + 1);
            float2 p = *reinterpret_cast<const float2*>(T + (size_t)c0 * 64 + lane * 2);
            float2 q = *reinterpret_cast<const float2*>(T + (size_t)c1 * 64 + lane * 2);
            s.x += p.x + q.x; s.y += p.y + q.y;
        }
        if (k < m) {
            int c0 = __shfl_sync(0xffffffffu, idx, k);
            float2 p = *reinterpret_cast<const float2*>(T + (size_t)c0 * 64 + lane * 2);
            s.x += p.x; s.y += p.y;
        }
    }
}

__global__ void __launch_bounds__(256) k_gather(float* __restrict__ out) {
    int row = blockIdx.x * 8 + (threadIdx.x >> 5);
    if (row >= NA + NB) return;
    int lane = threadIdx.x & 31;
    float2 s;
    if (row < NA) {
        int cself = __ldg(&g_cidA[row]);
        s = *reinterpret_cast<const float2*>(g_TzA + (size_t)cself * 64 + lane * 2);
        seg_sum(s, g_off[row],      g_off[row + 1],      g_Taa, lane);
        seg_sum(s, g_off[NA + row], g_off[NA + row + 1], g_Tba, lane);
    } else {
        int rb = row - NA;
        int cself = __ldg(&g_cidB[rb]);
        s = *reinterpret_cast<const float2*>(g_TzB + (size_t)cself * 64 + lane * 2);
        seg_sum(s, g_off[2 * NA + rb], g_off[2 * NA + rb + 1], g_Tab, lane);
    }
    s.x = fmaxf(s.x, 0.f); s.y = fmaxf(s.y, 0.f);
    *reinterpret_cast<float2*>(out + (size_t)row * 64 + lane * 2) = s;
}

// ==============================================================================
struct Aux {
    cudaStream_t s2;
    cudaEvent_t evF, evS, evJ;
    Aux() {
        cudaStreamCreateWithFlags(&s2, cudaStreamNonBlocking);
        cudaEventCreateWithFlags(&evF, cudaEventDisableTiming);
        cudaEventCreateWithFlags(&evS, cudaEventDisableTiming);
        cudaEventCreateWithFlags(&evJ, cudaEventDisableTiming);
    }
};

extern "C" void kernel_launch(void* const* d_in, const int* in_sizes, int n_in,
                              void* d_out, int out_size) {
    static Aux aux;   // stream/events created once (outside capture on first call)

    const int*   src_aa = (const int*)d_in[0];
    const int*   dst_aa = (const int*)d_in[1];
    const int*   src_ab = (const int*)d_in[2];
    const int*   dst_ab = (const int*)d_in[3];
    const int*   src_ba = (const int*)d_in[4];
    const int*   dst_ba = (const int*)d_in[5];
    const float* embA   = (const float*)d_in[6];
    const float* embB   = (const float*)d_in[7];
    const float* Waa    = (const float*)d_in[8];
    const float* baa    = (const float*)d_in[9];
    const float* Wab    = (const float*)d_in[10];
    const float* bab    = (const float*)d_in[11];
    const float* Wba    = (const float*)d_in[12];
    const float* bba    = (const float*)d_in[13];
    const float* WnA    = (const float*)d_in[14];
    const float* bnA    = (const float*)d_in[15];
    const float* WnB    = (const float*)d_in[16];
    const float* bnB    = (const float*)d_in[17];
    const int Eaa = in_sizes[0];
    const int Eab = in_sizes[2];
    const int Eba = in_sizes[4];
    const int Etot = Eaa + Eba + Eab;
    float* out = (float*)d_out;

    cudaFuncSetAttribute(k_gemmA, cudaFuncAttributeMaxDynamicSharedMemorySize, SMEM_A_BYTES);
    cudaFuncSetAttribute(k_gemmB, cudaFuncAttributeMaxDynamicSharedMemorySize, SMEM_B_BYTES);

    const float* Waa1 = Waa + 4096;
    const float* Wab1 = Wab + 4096;
    const float* Wba1 = Wba + 4096;
    const float* baa1 = baa + 64;
    const float* bab1 = bab + 64;
    const float* bba1 = bba + 64;
    const float* WnA1 = WnA + 192 * 64;
    const float* WnB1 = WnB + 128 * 64;
    const float* bnA1 = bnA + 64;
    const float* bnB1 = bnB + 64;

    // fork: combo-grid GEMMs depend only on weights -> side stream
    cudaEventRecord(aux.evF, 0);
    cudaStreamWaitEvent(aux.s2, aux.evF, 0);
    k_gemmA<<<CGRID / 128, 256, SMEM_A_BYTES, aux.s2>>>(
        embA, embB, Waa, baa, Wba, bba, WnA, bnA,
        Waa1, baa1, Wab1, bab1, WnA1, bnA1, WnB1 + 4096, 0);
    k_gemmB<<<CGRID / 128, 256, SMEM_B_BYTES, aux.s2>>>(
        embA, embB, Wab, bab, WnB, bnB,
        Wba1, bba1, WnB1, bnB1, WnA1 + 2 * 4096, 0);

    // main chain: deg -> single-pass scan+cid
    k_deg_all<<<(Etot + 255) / 256, 256>>>(dst_aa, Eaa, dst_ba, Eba, dst_ab, Eab);
    k_scan_cid<<<SCAN_NBLK, 1024>>>();

    // overflow GEMM rows (depend on scan) on side stream, concurrent with fill
    cudaEventRecord(aux.evS, 0);
    cudaStreamWaitEvent(aux.s2, aux.evS, 0);
    k_gemmA<<<(NA + 127) / 128, 256, SMEM_A_BYTES, aux.s2>>>(
        embA, embB, Waa, baa, Wba, bba, WnA, bnA,
        Waa1, baa1, Wab1, bab1, WnA1, bnA1, WnB1 + 4096, 1);
    k_gemmB<<<(NB + 127) / 128, 256, SMEM_B_BYTES, aux.s2>>>(
        embA, embB, Wab, bab, WnB, bnB,
        Wba1, bba1, WnB1, bnB1, WnA1 + 2 * 4096, 1);
    cudaEventRecord(aux.evJ, aux.s2);

    k_fill_all<<<(Etot + 255) / 256, 256>>>(src_aa, dst_aa, Eaa,
                                            src_ba, dst_ba, Eba,
                                            src_ab, dst_ab, Eab);

    // join, gather, then reset scratch for the next run
    cudaStreamWaitEvent(0, aux.evJ, 0);
    k_gather<<<(NA + NB + 7) / 8, 256>>>(out);
    k_zero_end<<<(NTOT / 4 + 255) / 256, 256>>>();
}